// round 2
// baseline (speedup 1.0000x reference)
#include <cuda_runtime.h>
#include <stdint.h>

#define JAX_PARTITIONABLE 1

#define BSZ   2
#define CH    64
#define FLATN 16384
#define NPTS  2048
#define KSMP  256
#define HID   32
#define TN    8      // points per pair-block
#define PT    8      // points per gxifeat-block

// ---------------- device scratch ------------------------------------------
__device__ float g_xi    [BSZ*NPTS*CH];
__device__ float g_mpe   [BSZ*NPTS*CH];
__device__ float g_A1    [BSZ*NPTS*HID];
__device__ float g_prob  [BSZ*NPTS];
__device__ float g_logp  [BSZ*NPTS];
__device__ float g_B1T   [BSZ*HID*KSMP];   // [b][i][k]
__device__ float g_tf    [BSZ*KSMP*CH];
__device__ float g_nek   [BSZ*KSMP];
__device__ float g_ctx   [BSZ*NPTS*CH];    // projected ctx contribution (64-dim)
__device__ float g_Weff  [4*CH*CH];        // w_r1 @ w_r2
__device__ float g_beff  [CH];
__device__ float g_s1[HID], g_bias1[HID], g_W2T[HID*HID], g_bias2[HID];
__device__ float g_sne[HID], g_biasne[HID];

// ---------------- helpers ---------------------------------------------------
__device__ __forceinline__ float warpsum(float v) {
    #pragma unroll
    for (int o = 16; o > 0; o >>= 1) v += __shfl_xor_sync(0xffffffffu, v, o);
    return v;
}
__device__ __forceinline__ uint32_t rotl32(uint32_t x, int d) {
    return (x << d) | (x >> (32 - d));
}
__device__ __forceinline__ void tf2x32(uint32_t k0, uint32_t k1,
                                       uint32_t x0, uint32_t x1,
                                       uint32_t& o0, uint32_t& o1) {
    uint32_t ks0 = k0, ks1 = k1, ks2 = k0 ^ k1 ^ 0x1BD11BDAu;
    x0 += ks0; x1 += ks1;
#define TF_RND(r) { x0 += x1; x1 = rotl32(x1, r); x1 ^= x0; }
    TF_RND(13) TF_RND(15) TF_RND(26) TF_RND(6)  x0 += ks1; x1 += ks2 + 1u;
    TF_RND(17) TF_RND(29) TF_RND(16) TF_RND(24) x0 += ks2; x1 += ks0 + 2u;
    TF_RND(13) TF_RND(15) TF_RND(26) TF_RND(6)  x0 += ks0; x1 += ks1 + 3u;
    TF_RND(17) TF_RND(29) TF_RND(16) TF_RND(24) x0 += ks1; x1 += ks2 + 4u;
    TF_RND(13) TF_RND(15) TF_RND(26) TF_RND(6)  x0 += ks2; x1 += ks0 + 5u;
#undef TF_RND
    o0 = x0; o1 = x1;
}

// ---------------- weff + prep (fused): W_eff rows + BN folds ----------------
__global__ void weffprep_kernel(const float* w_r1, const float* w_r2,
                                const float* b_ne1, const float* g_ne, const float* be_ne,
                                const float* b_p1,  const float* g_p1, const float* be_p1,
                                const float* w_p2,  const float* b_p2, const float* g_p2,
                                const float* be_p2, const float* b_r1, const float* b_r2) {
    __shared__ float row[2*CH];
    int c = blockIdx.x, f = threadIdx.x;
    row[f]      = w_r1[c*2*CH + f];
    row[f + CH] = w_r1[c*2*CH + f + CH];
    __syncthreads();
    float acc = 0.f;
    #pragma unroll 8
    for (int m = 0; m < 2*CH; m++) acc = fmaf(row[m], w_r2[m*CH + f], acc);
    g_Weff[c*CH + f] = acc;

    if (blockIdx.x == 0) {
        int t = threadIdx.x;
        float inv = 1.0f / sqrtf(1.0f + 1e-5f);
        if (t < HID) {
            float sne = g_ne[t] * inv;
            g_sne[t] = sne;
            g_biasne[t] = fmaf(b_ne1[t], sne, be_ne[t]);
            float s1 = g_p1[t] * inv;
            g_s1[t] = s1;
            g_bias1[t] = fmaf(b_p1[t], s1, be_p1[t]);
            float s2 = g_p2[t] * inv;
            g_bias2[t] = fmaf(b_p2[t], s2, be_p2[t]);
            for (int i = 0; i < HID; i++)
                g_W2T[t*HID + i] = w_p2[i*HID + t] * s2;
        }
        if (t < CH) {
            float a2 = b_r2[t];
            for (int m = 0; m < 2*CH; m++) a2 = fmaf(b_r1[m], w_r2[m*CH + t], a2);
            g_beff[t] = a2;
        }
    }
}

// ---------------- dense output: out = input @ (Weff[0:64]+Weff[192:256]) ----
__global__ void __launch_bounds__(256) dense_kernel(const float* input, float* out) {
    __shared__ float X[CH*65];
    __shared__ __align__(16) float Wl[CH*CH];
    __shared__ float bl[CH];
    int b  = blockIdx.y;
    int v0 = blockIdx.x * 64;
    int t  = threadIdx.x;
    for (int q = t; q < CH*64; q += 256) {
        int c = q >> 6, vl = q & 63;
        X[c*65 + vl] = input[(b*CH + c)*FLATN + v0 + vl];
    }
    for (int q = t; q < CH*CH; q += 256) Wl[q] = g_Weff[q] + g_Weff[3*CH*CH + q];
    if (t < CH) bl[t] = g_beff[t];
    __syncthreads();

    int vl = t & 63, fb = (t >> 6) * 16;
    float acc[16];
    #pragma unroll
    for (int i = 0; i < 16; i++) acc[i] = bl[fb + i];
    for (int c = 0; c < CH; c++) {
        float xv = X[c*65 + vl];
        const float4* wr = reinterpret_cast<const float4*>(&Wl[c*CH + fb]);
        #pragma unroll
        for (int r = 0; r < 4; r++) {
            float4 w = wr[r];
            acc[4*r+0] = fmaf(xv, w.x, acc[4*r+0]);
            acc[4*r+1] = fmaf(xv, w.y, acc[4*r+1]);
            acc[4*r+2] = fmaf(xv, w.z, acc[4*r+2]);
            acc[4*r+3] = fmaf(xv, w.w, acc[4*r+3]);
        }
    }
    #pragma unroll
    for (int i = 0; i < 16; i++)
        out[(b*CH + fb + i)*FLATN + v0 + vl] = acc[i];
}

// ---------------- fused gather + PE + ne-prob + A1 (8 points/block) ---------
__global__ void __launch_bounds__(256) gxifeat_kernel(
        const float* input, const int* mask_idx,
        const float* w_ne1, const float* w_ne2, const float* b_ne2,
        const float* w_p1) {
    __shared__ float xs[PT][CH];
    __shared__ int   vs[PT];
    int b  = blockIdx.x / (NPTS/PT);
    int p0 = (blockIdx.x % (NPTS/PT)) * PT;
    int t  = threadIdx.x;
    if (t < PT) vs[t] = mask_idx[b*NPTS + p0 + t];
    __syncthreads();
    const float kc = -0.1439115683121279f;            // -ln(10000)/64
    #pragma unroll
    for (int idx = t; idx < PT*CH; idx += 256) {
        int p = idx >> 6, c = idx & 63;
        int v = vs[p];
        int j = c >> 1;
        float div = expf((float)(2*j) * kc);
        float ang = (float)v * div;
        float pe  = (c & 1) ? cosf(ang) : sinf(ang);
        float xi  = input[(b*CH + c)*FLATN + v] + pe;
        int bn = b*NPTS + p0 + p;
        g_xi [bn*CH + c] = xi;
        g_mpe[bn*CH + c] = pe;
        xs[p][c] = xi;
    }
    __syncthreads();
    int w = t >> 5, j = t & 31;                        // warp w -> point w
    float dn = 0.f, dp = 0.f;
    #pragma unroll
    for (int c = 0; c < CH; c++) {
        float x = xs[w][c];
        dn = fmaf(x, w_ne1[c*HID + j], dn);
        dp = fmaf(x, w_p1 [c*HID + j], dp);
    }
    int bn = b*NPTS + p0 + w;
    g_A1[bn*HID + j] = dp * g_s1[j];
    float h = fmaxf(fmaf(dn, g_sne[j], g_biasne[j]), 0.f);
    float s = warpsum(h * w_ne2[j]);
    if (j == 0) {
        float logit = s + b_ne2[0];
        float p = 1.f / (1.f + expf(-logit));
        g_prob[bn] = p;
        g_logp[bn] = logf(p);
    }
}

// ---------------- gumbel-max sampling + fused gather of sampled row ---------
__global__ void __launch_bounds__(256) samplegather_kernel(const float* w_p1) {
    int bi = blockIdx.x;
    int b  = bi / KSMP;
    int i  = bi % KSMP;
    int t  = threadIdx.x;

    uint32_t kb0, kb1;
#if JAX_PARTITIONABLE
    tf2x32(0u, 42u, 0u, (uint32_t)b, kb0, kb1);
#else
    uint32_t a0, a1, c0, c1;
    tf2x32(0u, 42u, 0u, 2u, a0, a1);
    tf2x32(0u, 42u, 1u, 3u, c0, c1);
    if (b == 0) { kb0 = a0; kb1 = c0; } else { kb0 = a1; kb1 = c1; }
#endif

    const float TINY = 1.1754943508222875e-38f;
    float best = -3.402823466e38f;
    int   bidx = 0x7fffffff;
    for (int n = t; n < NPTS; n += 256) {
        uint32_t m = (uint32_t)(i*NPTS + n);
        uint32_t o0, o1, bits;
#if JAX_PARTITIONABLE
        tf2x32(kb0, kb1, 0u, m, o0, o1);
        bits = o0 ^ o1;
#else
        const uint32_t half = (KSMP * NPTS) / 2;
        if (m < half) { tf2x32(kb0, kb1, m, m + half, o0, o1); bits = o0; }
        else          { tf2x32(kb0, kb1, m - half, m, o0, o1); bits = o1; }
#endif
        float f = __uint_as_float((bits >> 9) | 0x3f800000u) - 1.0f;
        float u = fmaxf(f + TINY, TINY);
        float g = -logf(-logf(u));
        float val = g + g_logp[b*NPTS + n];
        if (val > best) { best = val; bidx = n; }
    }
    __shared__ float sv[256];
    __shared__ int   si[256];
    __shared__ float ms[CH];
    sv[t] = best; si[t] = bidx;
    __syncthreads();
    for (int s = 128; s > 0; s >>= 1) {
        if (t < s) {
            if (sv[t+s] > sv[t] || (sv[t+s] == sv[t] && si[t+s] < si[t])) {
                sv[t] = sv[t+s]; si[t] = si[t+s];
            }
        }
        __syncthreads();
    }
    int n = si[0];
    int src = (b*NPTS + n)*CH;
    if (t < CH) {
        ms[t] = g_mpe[src + t];
        g_tf[bi*CH + t] = g_xi[src + t];
    }
    __syncthreads();
    if (t < HID) {
        float d = 0.f;
        #pragma unroll
        for (int c = 0; c < CH; c++) d = fmaf(ms[c], w_p1[c*HID + t], d);
        g_B1T[(b*HID + t)*KSMP + i] = d * g_s1[t];
    }
    if (t == 0) g_nek[bi] = g_prob[b*NPTS + n];
}

// ---------------- heavy pairwise kernel: TN points per block ----------------
__global__ void __launch_bounds__(256, 2) pair_kernel(const float* w_p3, const float* b_p3) {
    __shared__ __align__(16) float W2s[HID*HID];       // 4KB
    __shared__ __align__(16) float SA[2*CH*CH];        // 32KB: B1 -> psI/psE -> Weff
    __shared__ float A1s[TN*HID];                      // 1KB
    __shared__ __align__(16) float wiS[KSMP*TN];       // 8KB  [k][n]
    __shared__ __align__(16) float weS[KSMP*TN];       // 8KB
    __shared__ float neS[KSMP];
    __shared__ float xa[TN*CH], xb[TN*CH];             // 4KB
    __shared__ float b1s[HID], b2s[HID], w3s[HID];
    __shared__ float sums[TN*2];
    __shared__ float bp3;

    int blk = blockIdx.x;
    int b   = blk / (NPTS/TN);
    int n0  = (blk % (NPTS/TN)) * TN;
    int t   = threadIdx.x;

    for (int q = t; q < HID*HID; q += 256) W2s[q] = g_W2T[q];
    for (int q = t; q < HID*KSMP; q += 256) SA[q] = g_B1T[b*HID*KSMP + q];  // SA[i*256+k]
    if (t < TN*HID) A1s[t] = g_A1[(b*NPTS + n0)*HID + t];
    if (t < HID) { b1s[t] = g_bias1[t]; b2s[t] = g_bias2[t]; w3s[t] = w_p3[t]; }
    if (t == 0) bp3 = b_p3[0];
    neS[t] = g_nek[b*KSMP + t];
    __syncthreads();

    // hoist B1 column (per-k) + bias into registers, reused across all TN points
    float B1r[HID];
    #pragma unroll
    for (int i = 0; i < HID; i++) B1r[i] = SA[i*KSMP + t] + b1s[i];

    float ne = neS[t];
    #pragma unroll 1
    for (int n = 0; n < TN; n++) {
        float h1[HID];
        #pragma unroll
        for (int i = 0; i < HID; i++)
            h1[i] = fmaxf(A1s[n*HID + i] + B1r[i], 0.f);
        float accP = 0.f;
        #pragma unroll
        for (int j = 0; j < HID; j++) {
            float z = b2s[j];
            const float4* wv = reinterpret_cast<const float4*>(&W2s[j*HID]);
            #pragma unroll
            for (int q = 0; q < 8; q++) {
                float4 w = wv[q];
                z = fmaf(h1[4*q+0], w.x, z);
                z = fmaf(h1[4*q+1], w.y, z);
                z = fmaf(h1[4*q+2], w.z, z);
                z = fmaf(h1[4*q+3], w.w, z);
            }
            accP = fmaf(fmaxf(z, 0.f), w3s[j], accP);
        }
        float P = 1.f / (1.f + expf(-(accP + bp3)));
        wiS[t*TN + n] = P * ne;
        weS[t*TN + n] = (1.f - P) * ne;
    }
    __syncthreads();

    // per-point scalar sums (warp w -> point w)
    {
        int w = t >> 5, lane = t & 31;
        float si = 0.f, se = 0.f;
        #pragma unroll
        for (int kk = lane; kk < KSMP; kk += 32) {
            si += wiS[kk*TN + w];
            se += weS[kk*TN + w];
        }
        si = warpsum(si); se = warpsum(se);
        if (lane == 0) { sums[w*2] = si; sums[w*2 + 1] = se; }
    }
    __syncthreads();

    // weighted sums over tf (quarter q of k, channel c)
    {
        int c = t & 63, q = t >> 6;
        float accI[TN], accE[TN];
        #pragma unroll
        for (int n = 0; n < TN; n++) { accI[n] = 0.f; accE[n] = 0.f; }
        const float* tfb = g_tf + b*KSMP*CH;
        for (int kk = q*64; kk < q*64 + 64; kk++) {
            float tfv = tfb[kk*CH + c];
            float4 wi0 = *reinterpret_cast<const float4*>(&wiS[kk*TN]);
            float4 wi1 = *reinterpret_cast<const float4*>(&wiS[kk*TN + 4]);
            float4 we0 = *reinterpret_cast<const float4*>(&weS[kk*TN]);
            float4 we1 = *reinterpret_cast<const float4*>(&weS[kk*TN + 4]);
            accI[0] = fmaf(wi0.x, tfv, accI[0]);
            accI[1] = fmaf(wi0.y, tfv, accI[1]);
            accI[2] = fmaf(wi0.z, tfv, accI[2]);
            accI[3] = fmaf(wi0.w, tfv, accI[3]);
            accI[4] = fmaf(wi1.x, tfv, accI[4]);
            accI[5] = fmaf(wi1.y, tfv, accI[5]);
            accI[6] = fmaf(wi1.z, tfv, accI[6]);
            accI[7] = fmaf(wi1.w, tfv, accI[7]);
            accE[0] = fmaf(we0.x, tfv, accE[0]);
            accE[1] = fmaf(we0.y, tfv, accE[1]);
            accE[2] = fmaf(we0.z, tfv, accE[2]);
            accE[3] = fmaf(we0.w, tfv, accE[3]);
            accE[4] = fmaf(we1.x, tfv, accE[4]);
            accE[5] = fmaf(we1.y, tfv, accE[5]);
            accE[6] = fmaf(we1.z, tfv, accE[6]);
            accE[7] = fmaf(we1.w, tfv, accE[7]);
        }
        // partials into SA (B1 no longer needed)
        #pragma unroll
        for (int n = 0; n < TN; n++) {
            SA[t*TN + n]        = accI[n];
            SA[2048 + t*TN + n] = accE[n];
        }
    }
    __syncthreads();

    // reduce quarters, normalize
    for (int idx = t; idx < TN*CH; idx += 256) {
        int n = idx >> 6, cc = idx & 63;
        float si = 0.f, se = 0.f;
        #pragma unroll
        for (int qq = 0; qq < 4; qq++) {
            si += SA[(qq*64 + cc)*TN + n];
            se += SA[2048 + (qq*64 + cc)*TN + n];
        }
        xa[n*CH + cc] = si / sums[n*2];
        xb[n*CH + cc] = se / sums[n*2 + 1];
    }
    __syncthreads();

    // ctx projection: Weff rows [64:192) into SA, project 128->64 per point
    for (int q = t; q < 2*CH*CH; q += 256) SA[q] = g_Weff[CH*CH + q];
    __syncthreads();
    for (int idx = t; idx < TN*CH; idx += 256) {
        int n = idx >> 6, f = idx & 63;
        float acc = 0.f;
        #pragma unroll 8
        for (int j = 0; j < CH; j++) {
            acc = fmaf(xa[n*CH + j], SA[j*CH + f], acc);
            acc = fmaf(xb[n*CH + j], SA[CH*CH + j*CH + f], acc);
        }
        g_ctx[(b*NPTS + n0 + n)*CH + f] = acc;
    }
}

// ---------------- sparse scatter of precomputed ctx -------------------------
__global__ void __launch_bounds__(256) scatter_kernel(const int* mask_idx, float* out) {
    int idx = blockIdx.x * 256 + threadIdx.x;       // over BSZ*NPTS*CH
    int bn  = idx >> 6;
    int f   = idx & 63;
    int b   = bn >> 11;                              // / NPTS
    int v   = mask_idx[bn];
    out[(b*CH + f)*FLATN + v] += g_ctx[idx];
}

// -----------------------------------------------------------------------------
extern "C" void kernel_launch(void* const* d_in, const int* in_sizes, int n_in,
                              void* d_out, int out_size) {
    const float* input    = (const float*)d_in[0];
    const int*   mask_idx = (const int*)  d_in[1];
    const float* w_ne1 = (const float*)d_in[2];
    const float* b_ne1 = (const float*)d_in[3];
    const float* g_ne  = (const float*)d_in[4];
    const float* be_ne = (const float*)d_in[5];
    const float* w_ne2 = (const float*)d_in[6];
    const float* b_ne2 = (const float*)d_in[7];
    const float* w_p1  = (const float*)d_in[8];
    const float* b_p1  = (const float*)d_in[9];
    const float* g_p1  = (const float*)d_in[10];
    const float* be_p1 = (const float*)d_in[11];
    const float* w_p2  = (const float*)d_in[12];
    const float* b_p2  = (const float*)d_in[13];
    const float* g_p2  = (const float*)d_in[14];
    const float* be_p2 = (const float*)d_in[15];
    const float* w_p3  = (const float*)d_in[16];
    const float* b_p3  = (const float*)d_in[17];
    const float* w_r1  = (const float*)d_in[18];
    const float* b_r1  = (const float*)d_in[19];
    const float* w_r2  = (const float*)d_in[20];
    const float* b_r2  = (const float*)d_in[21];
    float* out = (float*)d_out;

    weffprep_kernel<<<4*CH, CH>>>(w_r1, w_r2, b_ne1, g_ne, be_ne,
                                  b_p1, g_p1, be_p1, w_p2, b_p2, g_p2, be_p2,
                                  b_r1, b_r2);
    dense_kernel<<<dim3(FLATN/64, BSZ), 256>>>(input, out);    // warms L2 with input
    gxifeat_kernel<<<BSZ*NPTS/PT, 256>>>(input, mask_idx, w_ne1, w_ne2, b_ne2, w_p1);
    samplegather_kernel<<<BSZ*KSMP, 256>>>(w_p1);
    pair_kernel<<<BSZ*NPTS/TN, 256>>>(w_p3, b_p3);
    scatter_kernel<<<BSZ*NPTS*CH/256, 256>>>(mask_idx, out);
}

// round 3
// speedup vs baseline: 1.0748x; 1.0748x over previous
#include <cuda_runtime.h>
#include <stdint.h>

#define JAX_PARTITIONABLE 1

#define BSZ   2
#define CH    64
#define FLATN 16384
#define NPTS  2048
#define KSMP  256
#define HID   32
#define TN    8      // points per pair-block
#define PT    8      // points per gxifeat/projscatter block

typedef unsigned long long u64;

// ---------------- device scratch ------------------------------------------
__device__ float g_xi    [BSZ*NPTS*CH];
__device__ float g_mpe   [BSZ*NPTS*CH];
__device__ float g_A1    [BSZ*NPTS*HID];
__device__ float g_prob  [BSZ*NPTS];
__device__ float g_logp  [BSZ*NPTS];
__device__ float g_B1    [BSZ*KSMP*HID];   // [b][k][i], bias1 folded in
__device__ float g_tf    [BSZ*KSMP*CH];
__device__ float g_nek   [BSZ*KSMP];
__device__ float g_xintra[BSZ*NPTS*CH];
__device__ float g_xinter[BSZ*NPTS*CH];
__device__ float g_Weff  [4*CH*CH];        // w_r1 @ w_r2
__device__ float g_beff  [CH];
__device__ float g_s1[HID], g_bias1[HID], g_W2T[HID*HID], g_bias2[HID];
__device__ float g_sne[HID], g_biasne[HID];

// ---------------- helpers ---------------------------------------------------
__device__ __forceinline__ float warpsum(float v) {
    #pragma unroll
    for (int o = 16; o > 0; o >>= 1) v += __shfl_xor_sync(0xffffffffu, v, o);
    return v;
}
__device__ __forceinline__ u64 pack2(float lo, float hi) {
    u64 r; asm("mov.b64 %0, {%1,%2};" : "=l"(r) : "f"(lo), "f"(hi)); return r;
}
__device__ __forceinline__ void unpack2(u64 v, float& lo, float& hi) {
    asm("mov.b64 {%0,%1}, %2;" : "=f"(lo), "=f"(hi) : "l"(v));
}
__device__ __forceinline__ u64 fma2(u64 a, u64 b, u64 c) {
    u64 d; asm("fma.rn.f32x2 %0, %1, %2, %3;" : "=l"(d) : "l"(a), "l"(b), "l"(c)); return d;
}
__device__ __forceinline__ uint32_t rotl32(uint32_t x, int d) {
    return (x << d) | (x >> (32 - d));
}
__device__ __forceinline__ void tf2x32(uint32_t k0, uint32_t k1,
                                       uint32_t x0, uint32_t x1,
                                       uint32_t& o0, uint32_t& o1) {
    uint32_t ks0 = k0, ks1 = k1, ks2 = k0 ^ k1 ^ 0x1BD11BDAu;
    x0 += ks0; x1 += ks1;
#define TF_RND(r) { x0 += x1; x1 = rotl32(x1, r); x1 ^= x0; }
    TF_RND(13) TF_RND(15) TF_RND(26) TF_RND(6)  x0 += ks1; x1 += ks2 + 1u;
    TF_RND(17) TF_RND(29) TF_RND(16) TF_RND(24) x0 += ks2; x1 += ks0 + 2u;
    TF_RND(13) TF_RND(15) TF_RND(26) TF_RND(6)  x0 += ks0; x1 += ks1 + 3u;
    TF_RND(17) TF_RND(29) TF_RND(16) TF_RND(24) x0 += ks1; x1 += ks2 + 4u;
    TF_RND(13) TF_RND(15) TF_RND(26) TF_RND(6)  x0 += ks2; x1 += ks0 + 5u;
#undef TF_RND
    o0 = x0; o1 = x1;
}

// ---------------- weff + prep (fused) ---------------------------------------
__global__ void weffprep_kernel(const float* w_r1, const float* w_r2,
                                const float* b_ne1, const float* g_ne, const float* be_ne,
                                const float* b_p1,  const float* g_p1, const float* be_p1,
                                const float* w_p2,  const float* b_p2, const float* g_p2,
                                const float* be_p2, const float* b_r1, const float* b_r2) {
    __shared__ float row[2*CH];
    int c = blockIdx.x, f = threadIdx.x;
    row[f]      = w_r1[c*2*CH + f];
    row[f + CH] = w_r1[c*2*CH + f + CH];
    __syncthreads();
    float acc = 0.f;
    #pragma unroll 8
    for (int m = 0; m < 2*CH; m++) acc = fmaf(row[m], w_r2[m*CH + f], acc);
    g_Weff[c*CH + f] = acc;

    if (blockIdx.x == 0) {
        int t = threadIdx.x;
        float inv = 1.0f / sqrtf(1.0f + 1e-5f);
        if (t < HID) {
            float sne = g_ne[t] * inv;
            g_sne[t] = sne;
            g_biasne[t] = fmaf(b_ne1[t], sne, be_ne[t]);
            float s1 = g_p1[t] * inv;
            g_s1[t] = s1;
            g_bias1[t] = fmaf(b_p1[t], s1, be_p1[t]);
            float s2 = g_p2[t] * inv;
            g_bias2[t] = fmaf(b_p2[t], s2, be_p2[t]);
            for (int i = 0; i < HID; i++)
                g_W2T[t*HID + i] = w_p2[i*HID + t] * s2;
        }
        if (t < CH) {
            float a2 = b_r2[t];
            for (int m = 0; m < 2*CH; m++) a2 = fmaf(b_r1[m], w_r2[m*CH + t], a2);
            g_beff[t] = a2;
        }
    }
}

// ---------------- dense: out = input @ (Weff[0:64]+Weff[192:256]) + beff ----
__global__ void __launch_bounds__(256) dense_kernel(const float* input, float* out) {
    __shared__ float X[CH*65];
    __shared__ __align__(16) float Wl[CH*CH];
    __shared__ float bl[CH];
    int b  = blockIdx.y;
    int v0 = blockIdx.x * 64;
    int t  = threadIdx.x;
    for (int q = t; q < CH*64; q += 256) {
        int c = q >> 6, vl = q & 63;
        X[c*65 + vl] = input[(b*CH + c)*FLATN + v0 + vl];
    }
    for (int q = t; q < CH*CH; q += 256) Wl[q] = g_Weff[q] + g_Weff[3*CH*CH + q];
    if (t < CH) bl[t] = g_beff[t];
    __syncthreads();

    int vl = t & 63, fb = (t >> 6) * 16;
    u64 acc2[8];
    #pragma unroll
    for (int r = 0; r < 8; r++) acc2[r] = pack2(bl[fb + 2*r], bl[fb + 2*r + 1]);
    for (int c = 0; c < CH; c++) {
        float xv = X[c*65 + vl];
        u64 xp = pack2(xv, xv);
        const ulonglong2* wr = reinterpret_cast<const ulonglong2*>(&Wl[c*CH + fb]);
        #pragma unroll
        for (int r = 0; r < 4; r++) {
            ulonglong2 w = wr[r];
            acc2[2*r]   = fma2(xp, w.x, acc2[2*r]);
            acc2[2*r+1] = fma2(xp, w.y, acc2[2*r+1]);
        }
    }
    #pragma unroll
    for (int r = 0; r < 8; r++) {
        float lo, hi; unpack2(acc2[r], lo, hi);
        out[(b*CH + fb + 2*r    )*FLATN + v0 + vl] = lo;
        out[(b*CH + fb + 2*r + 1)*FLATN + v0 + vl] = hi;
    }
}

// ---------------- fused gather + PE + ne-prob + A1 (8 points/block) ---------
__global__ void __launch_bounds__(256) gxifeat_kernel(
        const float* input, const int* mask_idx,
        const float* w_ne1, const float* w_ne2, const float* b_ne2,
        const float* w_p1) {
    __shared__ float xs[PT][CH];
    __shared__ int   vs[PT];
    __shared__ float divs[HID];
    int b  = blockIdx.x / (NPTS/PT);
    int p0 = (blockIdx.x % (NPTS/PT)) * PT;
    int t  = threadIdx.x;
    const float kc = -0.1439115683121279f;            // -ln(10000)/64
    if (t < PT) vs[t] = mask_idx[b*NPTS + p0 + t];
    if (t < HID) divs[t] = expf((float)(2*t) * kc);
    __syncthreads();
    for (int idx = t; idx < PT*CH; idx += 256) {
        int p = idx >> 6, c = idx & 63;
        int v = vs[p];
        float ang = (float)v * divs[c >> 1];
        float pe  = (c & 1) ? cosf(ang) : sinf(ang);
        float xi  = input[(b*CH + c)*FLATN + v] + pe;
        int bn = b*NPTS + p0 + p;
        g_xi [bn*CH + c] = xi;
        g_mpe[bn*CH + c] = pe;
        xs[p][c] = xi;
    }
    __syncthreads();
    int w = t >> 5, j = t & 31;                        // warp w -> point w
    float dn = 0.f, dp = 0.f;
    #pragma unroll
    for (int c = 0; c < CH; c++) {
        float x = xs[w][c];
        dn = fmaf(x, w_ne1[c*HID + j], dn);
        dp = fmaf(x, w_p1 [c*HID + j], dp);
    }
    int bn = b*NPTS + p0 + w;
    g_A1[bn*HID + j] = dp * g_s1[j];
    float h = fmaxf(fmaf(dn, g_sne[j], g_biasne[j]), 0.f);
    float s = warpsum(h * w_ne2[j]);
    if (j == 0) {
        float logit = s + b_ne2[0];
        float p = 1.f / (1.f + expf(-logit));
        g_prob[bn] = p;
        g_logp[bn] = logf(p);
    }
}

// ---------------- gumbel-max sampling + gather of sampled row ---------------
__global__ void __launch_bounds__(512) samplegather_kernel(const float* w_p1) {
    int bi = blockIdx.x;
    int b  = bi >> 8;
    int i  = bi & 255;
    int t  = threadIdx.x;

    uint32_t kb0, kb1;
#if JAX_PARTITIONABLE
    tf2x32(0u, 42u, 0u, (uint32_t)b, kb0, kb1);
#else
    uint32_t a0, a1, c0, c1;
    tf2x32(0u, 42u, 0u, 2u, a0, a1);
    tf2x32(0u, 42u, 1u, 3u, c0, c1);
    if (b == 0) { kb0 = a0; kb1 = c0; } else { kb0 = a1; kb1 = c1; }
#endif

    const float TINY = 1.1754943508222875e-38f;
    float best = -3.402823466e38f;
    int   bidx = 0x7fffffff;
    for (int n = t; n < NPTS; n += 512) {
        uint32_t m = (uint32_t)(i*NPTS + n);
        uint32_t o0, o1, bits;
#if JAX_PARTITIONABLE
        tf2x32(kb0, kb1, 0u, m, o0, o1);
        bits = o0 ^ o1;
#else
        const uint32_t half = (KSMP * NPTS) / 2;
        if (m < half) { tf2x32(kb0, kb1, m, m + half, o0, o1); bits = o0; }
        else          { tf2x32(kb0, kb1, m - half, m, o0, o1); bits = o1; }
#endif
        float f = __uint_as_float((bits >> 9) | 0x3f800000u) - 1.0f;
        float u = fmaxf(f + TINY, TINY);
        float g = -logf(-logf(u));
        float val = g + g_logp[b*NPTS + n];
        if (val > best) { best = val; bidx = n; }
    }
    __shared__ float sv[512];
    __shared__ int   si[512];
    __shared__ float ms[CH];
    sv[t] = best; si[t] = bidx;
    __syncthreads();
    for (int s = 256; s > 0; s >>= 1) {
        if (t < s) {
            if (sv[t+s] > sv[t] || (sv[t+s] == sv[t] && si[t+s] < si[t])) {
                sv[t] = sv[t+s]; si[t] = si[t+s];
            }
        }
        __syncthreads();
    }
    int n = si[0];
    int src = (b*NPTS + n)*CH;
    if (t < CH) {
        ms[t] = g_mpe[src + t];
        g_tf[bi*CH + t] = g_xi[src + t];
    }
    __syncthreads();
    if (t < HID) {
        float d = 0.f;
        #pragma unroll
        for (int c = 0; c < CH; c++) d = fmaf(ms[c], w_p1[c*HID + t], d);
        g_B1[(b*KSMP + i)*HID + t] = fmaf(d, g_s1[t], g_bias1[t]);  // bias1 folded
    }
    if (t == 0) g_nek[bi] = g_prob[b*NPTS + n];
}

// ---------------- heavy pairwise kernel: TN points per block, f32x2 packed --
__global__ void __launch_bounds__(256) pair_kernel(const float* w_p3, const float* b_p3) {
    __shared__ __align__(16) float W2s[HID*HID];   // 4KB
    __shared__ __align__(16) float SB[4096];       // 16KB: wiwe(float2) -> partials
    __shared__ float A1s[TN*HID];                  // 1KB
    __shared__ float b2s[HID], w3s[HID];
    __shared__ float2 sums[TN];
    __shared__ float bp3s;

    int blk = blockIdx.x;
    int b   = blk / (NPTS/TN);
    int n0  = (blk % (NPTS/TN)) * TN;
    int t   = threadIdx.x;

    for (int q = t; q < HID*HID; q += 256) W2s[q] = g_W2T[q];
    if (t < TN*HID) A1s[t] = g_A1[(b*NPTS + n0)*HID + t];
    if (t < HID) { b2s[t] = g_bias2[t]; w3s[t] = w_p3[t]; }
    if (t == 0) bp3s = b_p3[0];

    // per-k B1 row (bias1 already folded)
    float B1[HID];
    {
        const float4* brow = reinterpret_cast<const float4*>(&g_B1[(b*KSMP + t)*HID]);
        #pragma unroll
        for (int q = 0; q < 8; q++) {
            float4 v = brow[q];
            B1[4*q] = v.x; B1[4*q+1] = v.y; B1[4*q+2] = v.z; B1[4*q+3] = v.w;
        }
    }
    float ne = g_nek[b*KSMP + t];
    __syncthreads();

    float2* wiwe = reinterpret_cast<float2*>(SB);
    #pragma unroll 1
    for (int n = 0; n < TN; n++) {
        u64 h1x2[HID/2];
        #pragma unroll
        for (int i2 = 0; i2 < HID/2; i2++) {
            float lo = fmaxf(A1s[n*HID + 2*i2]     + B1[2*i2],     0.f);
            float hi = fmaxf(A1s[n*HID + 2*i2 + 1] + B1[2*i2 + 1], 0.f);
            h1x2[i2] = pack2(lo, hi);
        }
        float accP = 0.f;
        #pragma unroll
        for (int j = 0; j < HID; j++) {
            const ulonglong2* wp = reinterpret_cast<const ulonglong2*>(&W2s[j*HID]);
            u64 z2 = pack2(b2s[j], 0.f);
            #pragma unroll
            for (int q = 0; q < 8; q++) {
                ulonglong2 w = wp[q];
                z2 = fma2(h1x2[2*q],     w.x, z2);
                z2 = fma2(h1x2[2*q + 1], w.y, z2);
            }
            float zl, zh; unpack2(z2, zl, zh);
            accP = fmaf(fmaxf(zl + zh, 0.f), w3s[j], accP);
        }
        float P = 1.f / (1.f + expf(-(accP + bp3s)));
        wiwe[n*KSMP + t] = make_float2(P * ne, (1.f - P) * ne);
    }
    __syncthreads();

    // per-point scalar sums (warp w -> point w)
    {
        int w = t >> 5, lane = t & 31;
        float si2 = 0.f, se2 = 0.f;
        #pragma unroll
        for (int kk = lane; kk < KSMP; kk += 32) {
            float2 v = wiwe[w*KSMP + kk];
            si2 += v.x; se2 += v.y;
        }
        si2 = warpsum(si2); se2 = warpsum(se2);
        if (lane == 0) sums[w] = make_float2(si2, se2);
    }

    // weighted sums over tf: packed {pi,pe} per n, quarter q of k, channel c
    u64 acc2[TN];
    {
        int c = t & 63, q = t >> 6;
        #pragma unroll
        for (int n = 0; n < TN; n++) acc2[n] = 0ULL;
        const float* tfb = g_tf + b*KSMP*CH;
        const u64* wv = reinterpret_cast<const u64*>(SB);
        for (int kk = q*64; kk < q*64 + 64; kk++) {
            float tfv = tfb[kk*CH + c];
            u64 t2 = pack2(tfv, tfv);
            #pragma unroll
            for (int n = 0; n < TN; n++)
                acc2[n] = fma2(t2, wv[n*KSMP + kk], acc2[n]);
        }
    }
    __syncthreads();          // all reads of wiwe done; SB reused for partials
    #pragma unroll
    for (int n = 0; n < TN; n++) {
        float pi, pe; unpack2(acc2[n], pi, pe);
        SB[t*TN + n]        = pi;
        SB[2048 + t*TN + n] = pe;
    }
    __syncthreads();

    for (int idx = t; idx < TN*CH; idx += 256) {
        int n = idx >> 6, c = idx & 63;
        float si2 = 0.f, se2 = 0.f;
        #pragma unroll
        for (int qq = 0; qq < 4; qq++) {
            int tt = qq*64 + c;
            si2 += SB[tt*TN + n];
            se2 += SB[2048 + tt*TN + n];
        }
        float2 s = sums[n];
        int gi = (b*NPTS + n0 + n)*CH + c;
        g_xintra[gi] = si2 / s.x;
        g_xinter[gi] = se2 / s.y;
    }
}

// ---------------- projection + scatter: 8 points/block, Weff in shared ------
__global__ void __launch_bounds__(256) projscatter_kernel(const int* mask_idx, float* out) {
    __shared__ __align__(16) float Wf[2*CH*CH];    // 32KB: Weff rows [64:192)
    __shared__ float xa[PT*CH], xb[PT*CH];
    __shared__ int vs[PT];
    int blk = blockIdx.x;
    int b   = blk / (NPTS/PT);
    int p0  = (blk % (NPTS/PT)) * PT;
    int t   = threadIdx.x;
    for (int q = t; q < 2*CH*CH; q += 256) Wf[q] = g_Weff[CH*CH + q];
    for (int q = t; q < PT*CH; q += 256) {
        xa[q] = g_xintra[(b*NPTS + p0)*CH + q];
        xb[q] = g_xinter[(b*NPTS + p0)*CH + q];
    }
    if (t < PT) vs[t] = mask_idx[b*NPTS + p0 + t];
    __syncthreads();
    for (int idx = t; idx < PT*CH; idx += 256) {
        int n = idx >> 6, f = idx & 63;
        float acc = 0.f;
        #pragma unroll 8
        for (int j = 0; j < CH; j++) {
            acc = fmaf(xa[n*CH + j], Wf[j*CH + f], acc);
            acc = fmaf(xb[n*CH + j], Wf[CH*CH + j*CH + f], acc);
        }
        out[(b*CH + f)*FLATN + vs[n]] += acc;
    }
}

// -----------------------------------------------------------------------------
extern "C" void kernel_launch(void* const* d_in, const int* in_sizes, int n_in,
                              void* d_out, int out_size) {
    const float* input    = (const float*)d_in[0];
    const int*   mask_idx = (const int*)  d_in[1];
    const float* w_ne1 = (const float*)d_in[2];
    const float* b_ne1 = (const float*)d_in[3];
    const float* g_ne  = (const float*)d_in[4];
    const float* be_ne = (const float*)d_in[5];
    const float* w_ne2 = (const float*)d_in[6];
    const float* b_ne2 = (const float*)d_in[7];
    const float* w_p1  = (const float*)d_in[8];
    const float* b_p1  = (const float*)d_in[9];
    const float* g_p1  = (const float*)d_in[10];
    const float* be_p1 = (const float*)d_in[11];
    const float* w_p2  = (const float*)d_in[12];
    const float* b_p2  = (const float*)d_in[13];
    const float* g_p2  = (const float*)d_in[14];
    const float* be_p2 = (const float*)d_in[15];
    const float* w_p3  = (const float*)d_in[16];
    const float* b_p3  = (const float*)d_in[17];
    const float* w_r1  = (const float*)d_in[18];
    const float* b_r1  = (const float*)d_in[19];
    const float* w_r2  = (const float*)d_in[20];
    const float* b_r2  = (const float*)d_in[21];
    float* out = (float*)d_out;

    weffprep_kernel<<<4*CH, CH>>>(w_r1, w_r2, b_ne1, g_ne, be_ne,
                                  b_p1, g_p1, be_p1, w_p2, b_p2, g_p2, be_p2,
                                  b_r1, b_r2);
    dense_kernel<<<dim3(FLATN/64, BSZ), 256>>>(input, out);
    gxifeat_kernel<<<BSZ*NPTS/PT, 256>>>(input, mask_idx, w_ne1, w_ne2, b_ne2, w_p1);
    samplegather_kernel<<<BSZ*KSMP, 512>>>(w_p1);
    pair_kernel<<<BSZ*NPTS/TN, 256>>>(w_p3, b_p3);
    projscatter_kernel<<<BSZ*NPTS/PT, 256>>>(mask_idx, out);
}

// round 4
// speedup vs baseline: 6.1541x; 5.7255x over previous
#include <cuda_runtime.h>
#include <stdint.h>

#define JAX_PARTITIONABLE 1

#define BSZ   2
#define CH    64
#define FLATN 16384
#define NPTS  2048
#define KSMP  256
#define HID   32
#define PT    8      // points per gxifeat/projscatter block

typedef unsigned long long u64;

// ---------------- device scratch ------------------------------------------
__device__ float g_xi    [BSZ*NPTS*CH];
__device__ float g_mpe   [BSZ*NPTS*CH];
__device__ float g_A1    [BSZ*NPTS*HID];
__device__ float g_prob  [BSZ*NPTS];
__device__ float g_logp  [BSZ*NPTS];
__device__ float g_B1T   [BSZ*HID*KSMP];   // [b][i][k], bias1 folded in
__device__ float g_tf    [BSZ*KSMP*CH];
__device__ float g_nek   [BSZ*KSMP];
__device__ float g_xintra[BSZ*NPTS*CH];
__device__ float g_xinter[BSZ*NPTS*CH];
__device__ float g_Weff  [4*CH*CH];        // w_r1 @ w_r2
__device__ float g_beff  [CH];
__device__ float g_s1[HID], g_bias1[HID], g_W2T[HID*HID], g_bias2[HID];
__device__ float g_sne[HID], g_biasne[HID];

// ---------------- helpers ---------------------------------------------------
__device__ __forceinline__ float warpsum(float v) {
    #pragma unroll
    for (int o = 16; o > 0; o >>= 1) v += __shfl_xor_sync(0xffffffffu, v, o);
    return v;
}
__device__ __forceinline__ u64 pack2(float lo, float hi) {
    u64 r; asm("mov.b64 %0, {%1,%2};" : "=l"(r) : "f"(lo), "f"(hi)); return r;
}
__device__ __forceinline__ void unpack2(u64 v, float& lo, float& hi) {
    asm("mov.b64 {%0,%1}, %2;" : "=f"(lo), "=f"(hi) : "l"(v));
}
__device__ __forceinline__ u64 fma2(u64 a, u64 b, u64 c) {
    u64 d; asm("fma.rn.f32x2 %0, %1, %2, %3;" : "=l"(d) : "l"(a), "l"(b), "l"(c)); return d;
}
__device__ __forceinline__ uint32_t rotl32(uint32_t x, int d) {
    return (x << d) | (x >> (32 - d));
}
__device__ __forceinline__ void tf2x32(uint32_t k0, uint32_t k1,
                                       uint32_t x0, uint32_t x1,
                                       uint32_t& o0, uint32_t& o1) {
    uint32_t ks0 = k0, ks1 = k1, ks2 = k0 ^ k1 ^ 0x1BD11BDAu;
    x0 += ks0; x1 += ks1;
#define TF_RND(r) { x0 += x1; x1 = rotl32(x1, r); x1 ^= x0; }
    TF_RND(13) TF_RND(15) TF_RND(26) TF_RND(6)  x0 += ks1; x1 += ks2 + 1u;
    TF_RND(17) TF_RND(29) TF_RND(16) TF_RND(24) x0 += ks2; x1 += ks0 + 2u;
    TF_RND(13) TF_RND(15) TF_RND(26) TF_RND(6)  x0 += ks0; x1 += ks1 + 3u;
    TF_RND(17) TF_RND(29) TF_RND(16) TF_RND(24) x0 += ks1; x1 += ks2 + 4u;
    TF_RND(13) TF_RND(15) TF_RND(26) TF_RND(6)  x0 += ks2; x1 += ks0 + 5u;
#undef TF_RND
    o0 = x0; o1 = x1;
}

// ---------------- weff + prep (fused) ---------------------------------------
__global__ void weffprep_kernel(const float* w_r1, const float* w_r2,
                                const float* b_ne1, const float* g_ne, const float* be_ne,
                                const float* b_p1,  const float* g_p1, const float* be_p1,
                                const float* w_p2,  const float* b_p2, const float* g_p2,
                                const float* be_p2, const float* b_r1, const float* b_r2) {
    __shared__ float row[2*CH];
    int c = blockIdx.x, f = threadIdx.x;
    row[f]      = w_r1[c*2*CH + f];
    row[f + CH] = w_r1[c*2*CH + f + CH];
    __syncthreads();
    float acc = 0.f;
    #pragma unroll 8
    for (int m = 0; m < 2*CH; m++) acc = fmaf(row[m], w_r2[m*CH + f], acc);
    g_Weff[c*CH + f] = acc;

    if (blockIdx.x == 0) {
        int t = threadIdx.x;
        float inv = 1.0f / sqrtf(1.0f + 1e-5f);
        if (t < HID) {
            float sne = g_ne[t] * inv;
            g_sne[t] = sne;
            g_biasne[t] = fmaf(b_ne1[t], sne, be_ne[t]);
            float s1 = g_p1[t] * inv;
            g_s1[t] = s1;
            g_bias1[t] = fmaf(b_p1[t], s1, be_p1[t]);
            float s2 = g_p2[t] * inv;
            g_bias2[t] = fmaf(b_p2[t], s2, be_p2[t]);
            for (int i = 0; i < HID; i++)
                g_W2T[t*HID + i] = w_p2[i*HID + t] * s2;
        }
        if (t < CH) {
            float a2 = b_r2[t];
            for (int m = 0; m < 2*CH; m++) a2 = fmaf(b_r1[m], w_r2[m*CH + t], a2);
            g_beff[t] = a2;
        }
    }
}

// ---------------- fused gather + PE + ne-prob + A1 (8 points/block) ---------
__global__ void __launch_bounds__(256) gxifeat_kernel(
        const float* input, const int* mask_idx,
        const float* w_ne1, const float* w_ne2, const float* b_ne2,
        const float* w_p1) {
    __shared__ float xs[PT][CH];
    __shared__ int   vs[PT];
    __shared__ float divs[HID];
    int b  = blockIdx.x / (NPTS/PT);
    int p0 = (blockIdx.x % (NPTS/PT)) * PT;
    int t  = threadIdx.x;
    const float kc = -0.1439115683121279f;            // -ln(10000)/64
    if (t < PT) vs[t] = mask_idx[b*NPTS + p0 + t];
    if (t < HID) divs[t] = expf((float)(2*t) * kc);
    __syncthreads();
    for (int idx = t; idx < PT*CH; idx += 256) {
        int p = idx >> 6, c = idx & 63;
        int v = vs[p];
        float ang = (float)v * divs[c >> 1];
        float pe  = (c & 1) ? cosf(ang) : sinf(ang);
        float xi  = input[(b*CH + c)*FLATN + v] + pe;
        int bn = b*NPTS + p0 + p;
        g_xi [bn*CH + c] = xi;
        g_mpe[bn*CH + c] = pe;
        xs[p][c] = xi;
    }
    __syncthreads();
    int w = t >> 5, j = t & 31;                        // warp w -> point w
    float dn = 0.f, dp = 0.f;
    #pragma unroll
    for (int c = 0; c < CH; c++) {
        float x = xs[w][c];
        dn = fmaf(x, w_ne1[c*HID + j], dn);
        dp = fmaf(x, w_p1 [c*HID + j], dp);
    }
    int bn = b*NPTS + p0 + w;
    g_A1[bn*HID + j] = dp * g_s1[j];
    float h = fmaxf(fmaf(dn, g_sne[j], g_biasne[j]), 0.f);
    float s = warpsum(h * w_ne2[j]);
    if (j == 0) {
        float logit = s + b_ne2[0];
        float p = 1.f / (1.f + expf(-logit));
        g_prob[bn] = p;
        g_logp[bn] = logf(p);
    }
}

// ---------------- gumbel-max sampling + gather of sampled row ---------------
__global__ void __launch_bounds__(256) samplegather_kernel(const float* w_p1) {
    int bi = blockIdx.x;
    int b  = bi >> 8;
    int i  = bi & 255;
    int t  = threadIdx.x;

    uint32_t kb0, kb1;
#if JAX_PARTITIONABLE
    tf2x32(0u, 42u, 0u, (uint32_t)b, kb0, kb1);
#else
    uint32_t a0, a1, c0, c1;
    tf2x32(0u, 42u, 0u, 2u, a0, a1);
    tf2x32(0u, 42u, 1u, 3u, c0, c1);
    if (b == 0) { kb0 = a0; kb1 = c0; } else { kb0 = a1; kb1 = c1; }
#endif

    const float TINY = 1.1754943508222875e-38f;
    float best = -3.402823466e38f;
    int   bidx = 0x7fffffff;
    for (int n = t; n < NPTS; n += 256) {
        uint32_t m = (uint32_t)(i*NPTS + n);
        uint32_t o0, o1, bits;
#if JAX_PARTITIONABLE
        tf2x32(kb0, kb1, 0u, m, o0, o1);
        bits = o0 ^ o1;
#else
        const uint32_t half = (KSMP * NPTS) / 2;
        if (m < half) { tf2x32(kb0, kb1, m, m + half, o0, o1); bits = o0; }
        else          { tf2x32(kb0, kb1, m - half, m, o0, o1); bits = o1; }
#endif
        float f = __uint_as_float((bits >> 9) | 0x3f800000u) - 1.0f;
        float u = fmaxf(f + TINY, TINY);
        float g = -logf(-logf(u));
        float val = g + g_logp[b*NPTS + n];
        if (val > best) { best = val; bidx = n; }
    }
    __shared__ float sv[256];
    __shared__ int   si[256];
    __shared__ float ms[CH];
    sv[t] = best; si[t] = bidx;
    __syncthreads();
    for (int s = 128; s > 0; s >>= 1) {
        if (t < s) {
            if (sv[t+s] > sv[t] || (sv[t+s] == sv[t] && si[t+s] < si[t])) {
                sv[t] = sv[t+s]; si[t] = si[t+s];
            }
        }
        __syncthreads();
    }
    int n = si[0];
    int src = (b*NPTS + n)*CH;
    if (t < CH) {
        ms[t] = g_mpe[src + t];
        g_tf[bi*CH + t] = g_xi[src + t];
    }
    __syncthreads();
    if (t < HID) {
        float d = 0.f;
        #pragma unroll
        for (int c = 0; c < CH; c++) d = fmaf(ms[c], w_p1[c*HID + t], d);
        g_B1T[(b*HID + t)*KSMP + i] = fmaf(d, g_s1[t], g_bias1[t]);  // bias1 folded
    }
    if (t == 0) g_nek[bi] = g_prob[b*NPTS + n];
}

// ---------------- heavy pairwise kernel: ONE point per block (R1-proven) ----
__global__ void __launch_bounds__(256) pair_kernel(const float* w_p3, const float* b_p3) {
    __shared__ __align__(16) float  W2s[HID*HID];   // 4KB
    __shared__ __align__(16) float2 wiwe[KSMP];     // 2KB
    __shared__ __align__(16) float2 part[KSMP];     // 2KB
    __shared__ float A1s[HID], b2s[HID], w3s[HID];
    __shared__ float2 sumIE;
    __shared__ float bp3s;

    int bn = blockIdx.x;
    int b  = bn >> 11;                               // / NPTS
    int t  = threadIdx.x;                            // t = k

    for (int q = t; q < HID*HID; q += 256) W2s[q] = g_W2T[q];
    if (t < HID) {
        A1s[t] = g_A1[bn*HID + t];
        b2s[t] = g_bias2[t];
        w3s[t] = w_p3[t];
    }
    if (t == 0) bp3s = b_p3[0];
    float ne = g_nek[b*KSMP + t];
    __syncthreads();

    // h1 = relu(A1[n] + B1T[:,k]) packed in pairs (bias1 folded in B1T)
    u64 h1x2[HID/2];
    #pragma unroll
    for (int i2 = 0; i2 < HID/2; i2++) {
        float lo = fmaxf(A1s[2*i2]     + g_B1T[(b*HID + 2*i2    )*KSMP + t], 0.f);
        float hi = fmaxf(A1s[2*i2 + 1] + g_B1T[(b*HID + 2*i2 + 1)*KSMP + t], 0.f);
        h1x2[i2] = pack2(lo, hi);
    }

    // layer 2 (32x32, f32x2) + layer 3 (32->1)
    float accP = 0.f;
    #pragma unroll
    for (int j = 0; j < HID; j++) {
        const ulonglong2* wp = reinterpret_cast<const ulonglong2*>(&W2s[j*HID]);
        u64 z2 = pack2(b2s[j], 0.f);
        #pragma unroll
        for (int q = 0; q < 8; q++) {
            ulonglong2 w = wp[q];                    // broadcast LDS.128
            z2 = fma2(h1x2[2*q],     w.x, z2);
            z2 = fma2(h1x2[2*q + 1], w.y, z2);
        }
        float zl, zh; unpack2(z2, zl, zh);
        accP = fmaf(fmaxf(zl + zh, 0.f), w3s[j], accP);
    }
    float P = 1.f / (1.f + expf(-(accP + bp3s)));
    wiwe[t] = make_float2(P * ne, (1.f - P) * ne);
    __syncthreads();

    // warp 0: scalar sums of wi/we
    if (t < 32) {
        float si = 0.f, se = 0.f;
        #pragma unroll
        for (int kk = t; kk < KSMP; kk += 32) {
            float2 v = wiwe[kk];
            si += v.x; se += v.y;
        }
        si = warpsum(si); se = warpsum(se);
        if (t == 0) sumIE = make_float2(si, se);
    }

    // weighted sums over tf: quarter q of k, channel c, packed {pi,pe}
    {
        int c = t & 63, q = t >> 6;
        u64 acc2 = 0ULL;
        const float* tfb = g_tf + b*KSMP*CH;
        const u64* wv = reinterpret_cast<const u64*>(wiwe);
        #pragma unroll 4
        for (int kk = q*64; kk < q*64 + 64; kk++) {
            float tfv = tfb[kk*CH + c];
            acc2 = fma2(pack2(tfv, tfv), wv[kk], acc2);   // wv[kk]: broadcast LDS.64
        }
        float pi, pe; unpack2(acc2, pi, pe);
        part[t] = make_float2(pi, pe);
    }
    __syncthreads();

    if (t < CH) {
        float2 p0 = part[t], p1 = part[64 + t], p2 = part[128 + t], p3 = part[192 + t];
        float si = p0.x + p1.x + p2.x + p3.x;
        float se = p0.y + p1.y + p2.y + p3.y;
        float2 s = sumIE;
        g_xintra[bn*CH + t] = si / s.x;
        g_xinter[bn*CH + t] = se / s.y;
    }
}

// ---------------- dense: out = input @ (Weff[0:64]+Weff[192:256]) + beff ----
__global__ void __launch_bounds__(256) dense_kernel(const float* input, float* out) {
    __shared__ float X[CH*65];
    __shared__ __align__(16) float Wl[CH*CH];
    __shared__ float bl[CH];
    int b  = blockIdx.y;
    int v0 = blockIdx.x * 64;
    int t  = threadIdx.x;
    for (int q = t; q < CH*64; q += 256) {
        int c = q >> 6, vl = q & 63;
        X[c*65 + vl] = input[(b*CH + c)*FLATN + v0 + vl];
    }
    for (int q = t; q < CH*CH; q += 256) Wl[q] = g_Weff[q] + g_Weff[3*CH*CH + q];
    if (t < CH) bl[t] = g_beff[t];
    __syncthreads();

    int vl = t & 63, fb = (t >> 6) * 16;
    u64 acc2[8];
    #pragma unroll
    for (int r = 0; r < 8; r++) acc2[r] = pack2(bl[fb + 2*r], bl[fb + 2*r + 1]);
    for (int c = 0; c < CH; c++) {
        float xv = X[c*65 + vl];
        u64 xp = pack2(xv, xv);
        const ulonglong2* wr = reinterpret_cast<const ulonglong2*>(&Wl[c*CH + fb]);
        #pragma unroll
        for (int r = 0; r < 4; r++) {
            ulonglong2 w = wr[r];
            acc2[2*r]   = fma2(xp, w.x, acc2[2*r]);
            acc2[2*r+1] = fma2(xp, w.y, acc2[2*r+1]);
        }
    }
    #pragma unroll
    for (int r = 0; r < 8; r++) {
        float lo, hi; unpack2(acc2[r], lo, hi);
        out[(b*CH + fb + 2*r    )*FLATN + v0 + vl] = lo;
        out[(b*CH + fb + 2*r + 1)*FLATN + v0 + vl] = hi;
    }
}

// ---------------- projection + scatter: 8 points/block, Weff in shared ------
__global__ void __launch_bounds__(256) projscatter_kernel(const int* mask_idx, float* out) {
    __shared__ __align__(16) float Wf[2*CH*CH];    // 32KB: Weff rows [64:192)
    __shared__ float xa[PT*CH], xb[PT*CH];
    __shared__ int vs[PT];
    int blk = blockIdx.x;
    int b   = blk / (NPTS/PT);
    int p0  = (blk % (NPTS/PT)) * PT;
    int t   = threadIdx.x;
    for (int q = t; q < 2*CH*CH; q += 256) Wf[q] = g_Weff[CH*CH + q];
    for (int q = t; q < PT*CH; q += 256) {
        xa[q] = g_xintra[(b*NPTS + p0)*CH + q];
        xb[q] = g_xinter[(b*NPTS + p0)*CH + q];
    }
    if (t < PT) vs[t] = mask_idx[b*NPTS + p0 + t];
    __syncthreads();
    for (int idx = t; idx < PT*CH; idx += 256) {
        int n = idx >> 6, f = idx & 63;
        float acc = 0.f;
        #pragma unroll 8
        for (int j = 0; j < CH; j++) {
            acc = fmaf(xa[n*CH + j], Wf[j*CH + f], acc);
            acc = fmaf(xb[n*CH + j], Wf[CH*CH + j*CH + f], acc);
        }
        out[(b*CH + f)*FLATN + vs[n]] += acc;
    }
}

// -----------------------------------------------------------------------------
extern "C" void kernel_launch(void* const* d_in, const int* in_sizes, int n_in,
                              void* d_out, int out_size) {
    const float* input    = (const float*)d_in[0];
    const int*   mask_idx = (const int*)  d_in[1];
    const float* w_ne1 = (const float*)d_in[2];
    const float* b_ne1 = (const float*)d_in[3];
    const float* g_ne  = (const float*)d_in[4];
    const float* be_ne = (const float*)d_in[5];
    const float* w_ne2 = (const float*)d_in[6];
    const float* b_ne2 = (const float*)d_in[7];
    const float* w_p1  = (const float*)d_in[8];
    const float* b_p1  = (const float*)d_in[9];
    const float* g_p1  = (const float*)d_in[10];
    const float* be_p1 = (const float*)d_in[11];
    const float* w_p2  = (const float*)d_in[12];
    const float* b_p2  = (const float*)d_in[13];
    const float* g_p2  = (const float*)d_in[14];
    const float* be_p2 = (const float*)d_in[15];
    const float* w_p3  = (const float*)d_in[16];
    const float* b_p3  = (const float*)d_in[17];
    const float* w_r1  = (const float*)d_in[18];
    const float* b_r1  = (const float*)d_in[19];
    const float* w_r2  = (const float*)d_in[20];
    const float* b_r2  = (const float*)d_in[21];
    float* out = (float*)d_out;

    // pair is launch #4 so the harness ncu capture lands on it
    weffprep_kernel<<<4*CH, CH>>>(w_r1, w_r2, b_ne1, g_ne, be_ne,
                                  b_p1, g_p1, be_p1, w_p2, b_p2, g_p2, be_p2,
                                  b_r1, b_r2);
    gxifeat_kernel<<<BSZ*NPTS/PT, 256>>>(input, mask_idx, w_ne1, w_ne2, b_ne2, w_p1);
    samplegather_kernel<<<BSZ*KSMP, 256>>>(w_p1);
    pair_kernel<<<BSZ*NPTS, 256>>>(w_p3, b_p3);
    dense_kernel<<<dim3(FLATN/64, BSZ), 256>>>(input, out);
    projscatter_kernel<<<BSZ*NPTS/PT, 256>>>(mask_idx, out);
}

// round 5
// speedup vs baseline: 7.1522x; 1.1622x over previous
#include <cuda_runtime.h>
#include <stdint.h>

#define JAX_PARTITIONABLE 1

#define BSZ   2
#define CH    64
#define FLATN 16384
#define NPTS  2048
#define KSMP  256
#define HID   32
#define PT    8      // points per gxifeat/projscatter block

typedef unsigned long long u64;

// ---------------- device scratch ------------------------------------------
__device__ float g_xi    [BSZ*NPTS*CH];
__device__ float g_mpe   [BSZ*NPTS*CH];
__device__ float g_A1    [BSZ*NPTS*HID];
__device__ float g_prob  [BSZ*NPTS];
__device__ float g_logp  [BSZ*NPTS];
__device__ float g_B1T   [BSZ*HID*KSMP];   // [b][i][k], bias1 folded in
__device__ float g_tf    [BSZ*KSMP*CH];
__device__ float g_nek   [BSZ*KSMP];
__device__ float g_xintra[BSZ*NPTS*CH];
__device__ float g_xinter[BSZ*NPTS*CH];
__device__ float g_Weff  [4*CH*CH];        // w_r1 @ w_r2
__device__ float g_beff  [CH];
__device__ float g_s1[HID], g_bias1[HID], g_W2T[HID*HID], g_bias2[HID];
__device__ float g_sne[HID], g_biasne[HID];

// ---------------- helpers ---------------------------------------------------
__device__ __forceinline__ float warpsum(float v) {
    #pragma unroll
    for (int o = 16; o > 0; o >>= 1) v += __shfl_xor_sync(0xffffffffu, v, o);
    return v;
}
__device__ __forceinline__ u64 pack2(float lo, float hi) {
    u64 r; asm("mov.b64 %0, {%1,%2};" : "=l"(r) : "f"(lo), "f"(hi)); return r;
}
__device__ __forceinline__ void unpack2(u64 v, float& lo, float& hi) {
    asm("mov.b64 {%0,%1}, %2;" : "=f"(lo), "=f"(hi) : "l"(v));
}
__device__ __forceinline__ u64 fma2(u64 a, u64 b, u64 c) {
    u64 d; asm("fma.rn.f32x2 %0, %1, %2, %3;" : "=l"(d) : "l"(a), "l"(b), "l"(c)); return d;
}
__device__ __forceinline__ uint32_t rotl32(uint32_t x, int d) {
    return (x << d) | (x >> (32 - d));
}
__device__ __forceinline__ void tf2x32(uint32_t k0, uint32_t k1,
                                       uint32_t x0, uint32_t x1,
                                       uint32_t& o0, uint32_t& o1) {
    uint32_t ks0 = k0, ks1 = k1, ks2 = k0 ^ k1 ^ 0x1BD11BDAu;
    x0 += ks0; x1 += ks1;
#define TF_RND(r) { x0 += x1; x1 = rotl32(x1, r); x1 ^= x0; }
    TF_RND(13) TF_RND(15) TF_RND(26) TF_RND(6)  x0 += ks1; x1 += ks2 + 1u;
    TF_RND(17) TF_RND(29) TF_RND(16) TF_RND(24) x0 += ks2; x1 += ks0 + 2u;
    TF_RND(13) TF_RND(15) TF_RND(26) TF_RND(6)  x0 += ks0; x1 += ks1 + 3u;
    TF_RND(17) TF_RND(29) TF_RND(16) TF_RND(24) x0 += ks1; x1 += ks2 + 4u;
    TF_RND(13) TF_RND(15) TF_RND(26) TF_RND(6)  x0 += ks2; x1 += ks0 + 5u;
#undef TF_RND
    o0 = x0; o1 = x1;
}

// ---------------- weff + prep (fused) ---------------------------------------
__global__ void weffprep_kernel(const float* w_r1, const float* w_r2,
                                const float* b_ne1, const float* g_ne, const float* be_ne,
                                const float* b_p1,  const float* g_p1, const float* be_p1,
                                const float* w_p2,  const float* b_p2, const float* g_p2,
                                const float* be_p2, const float* b_r1, const float* b_r2) {
    __shared__ float row[2*CH];
    int c = blockIdx.x, f = threadIdx.x;
    row[f]      = w_r1[c*2*CH + f];
    row[f + CH] = w_r1[c*2*CH + f + CH];
    __syncthreads();
    float acc = 0.f;
    #pragma unroll 8
    for (int m = 0; m < 2*CH; m++) acc = fmaf(row[m], w_r2[m*CH + f], acc);
    g_Weff[c*CH + f] = acc;

    if (blockIdx.x == 0) {
        int t = threadIdx.x;
        float inv = 1.0f / sqrtf(1.0f + 1e-5f);
        if (t < HID) {
            float sne = g_ne[t] * inv;
            g_sne[t] = sne;
            g_biasne[t] = fmaf(b_ne1[t], sne, be_ne[t]);
            float s1 = g_p1[t] * inv;
            g_s1[t] = s1;
            g_bias1[t] = fmaf(b_p1[t], s1, be_p1[t]);
            float s2 = g_p2[t] * inv;
            g_bias2[t] = fmaf(b_p2[t], s2, be_p2[t]);
            for (int i = 0; i < HID; i++)
                g_W2T[t*HID + i] = w_p2[i*HID + t] * s2;
        }
        if (t < CH) {
            float a2 = b_r2[t];
            for (int m = 0; m < 2*CH; m++) a2 = fmaf(b_r1[m], w_r2[m*CH + t], a2);
            g_beff[t] = a2;
        }
    }
}

// ---------------- fused gather + PE + ne-prob + A1 (8 points/block) ---------
__global__ void __launch_bounds__(256) gxifeat_kernel(
        const float* input, const int* mask_idx,
        const float* w_ne1, const float* w_ne2, const float* b_ne2,
        const float* w_p1) {
    __shared__ float xs[PT][CH];
    __shared__ int   vs[PT];
    __shared__ float divs[HID];
    int b  = blockIdx.x / (NPTS/PT);
    int p0 = (blockIdx.x % (NPTS/PT)) * PT;
    int t  = threadIdx.x;
    const float kc = -0.1439115683121279f;            // -ln(10000)/64
    if (t < PT) vs[t] = mask_idx[b*NPTS + p0 + t];
    if (t < HID) divs[t] = expf((float)(2*t) * kc);
    __syncthreads();
    for (int idx = t; idx < PT*CH; idx += 256) {
        int p = idx >> 6, c = idx & 63;
        int v = vs[p];
        float ang = (float)v * divs[c >> 1];
        float pe  = (c & 1) ? cosf(ang) : sinf(ang);
        float xi  = input[(b*CH + c)*FLATN + v] + pe;
        int bn = b*NPTS + p0 + p;
        g_xi [bn*CH + c] = xi;
        g_mpe[bn*CH + c] = pe;
        xs[p][c] = xi;
    }
    __syncthreads();
    int w = t >> 5, j = t & 31;                        // warp w -> point w
    float dn = 0.f, dp = 0.f;
    #pragma unroll
    for (int c = 0; c < CH; c++) {
        float x = xs[w][c];
        dn = fmaf(x, w_ne1[c*HID + j], dn);
        dp = fmaf(x, w_p1 [c*HID + j], dp);
    }
    int bn = b*NPTS + p0 + w;
    g_A1[bn*HID + j] = dp * g_s1[j];
    float h = fmaxf(fmaf(dn, g_sne[j], g_biasne[j]), 0.f);
    float s = warpsum(h * w_ne2[j]);
    if (j == 0) {
        float logit = s + b_ne2[0];
        float p = 1.f / (1.f + expf(-logit));
        g_prob[bn] = p;
        g_logp[bn] = logf(p);
    }
}

// ---------------- gumbel-max sampling + gather of sampled row ---------------
__global__ void __launch_bounds__(256) samplegather_kernel(const float* w_p1) {
    int bi = blockIdx.x;
    int b  = bi >> 8;
    int i  = bi & 255;
    int t  = threadIdx.x;

    uint32_t kb0, kb1;
#if JAX_PARTITIONABLE
    tf2x32(0u, 42u, 0u, (uint32_t)b, kb0, kb1);
#else
    uint32_t a0, a1, c0, c1;
    tf2x32(0u, 42u, 0u, 2u, a0, a1);
    tf2x32(0u, 42u, 1u, 3u, c0, c1);
    if (b == 0) { kb0 = a0; kb1 = c0; } else { kb0 = a1; kb1 = c1; }
#endif

    const float TINY = 1.1754943508222875e-38f;
    float best = -3.402823466e38f;
    int   bidx = 0x7fffffff;
    for (int n = t; n < NPTS; n += 256) {
        uint32_t m = (uint32_t)(i*NPTS + n);
        uint32_t o0, o1, bits;
#if JAX_PARTITIONABLE
        tf2x32(kb0, kb1, 0u, m, o0, o1);
        bits = o0 ^ o1;
#else
        const uint32_t half = (KSMP * NPTS) / 2;
        if (m < half) { tf2x32(kb0, kb1, m, m + half, o0, o1); bits = o0; }
        else          { tf2x32(kb0, kb1, m - half, m, o0, o1); bits = o1; }
#endif
        float f = __uint_as_float((bits >> 9) | 0x3f800000u) - 1.0f;
        float u = fmaxf(f + TINY, TINY);
        float g = -logf(-logf(u));
        float val = g + g_logp[b*NPTS + n];
        if (val > best) { best = val; bidx = n; }
    }
    __shared__ float sv[256];
    __shared__ int   si[256];
    __shared__ float ms[CH];
    sv[t] = best; si[t] = bidx;
    __syncthreads();
    for (int s = 128; s > 0; s >>= 1) {
        if (t < s) {
            if (sv[t+s] > sv[t] || (sv[t+s] == sv[t] && si[t+s] < si[t])) {
                sv[t] = sv[t+s]; si[t] = si[t+s];
            }
        }
        __syncthreads();
    }
    int n = si[0];
    int src = (b*NPTS + n)*CH;
    if (t < CH) {
        ms[t] = g_mpe[src + t];
        g_tf[bi*CH + t] = g_xi[src + t];
    }
    __syncthreads();
    if (t < HID) {
        float d = 0.f;
        #pragma unroll
        for (int c = 0; c < CH; c++) d = fmaf(ms[c], w_p1[c*HID + t], d);
        g_B1T[(b*HID + t)*KSMP + i] = fmaf(d, g_s1[t], g_bias1[t]);  // bias1 folded
    }
    if (t == 0) g_nek[bi] = g_prob[b*NPTS + n];
}

// ---------------- heavy pairwise kernel: 2 points per block, shared W2 LDS --
__global__ void __launch_bounds__(256) pair_kernel(const float* w_p3, const float* b_p3) {
    __shared__ __align__(16) float  W2s[HID*HID];    // 4KB
    __shared__ __align__(16) float2 wiwe[2][KSMP];   // 4KB
    __shared__ __align__(16) float2 part[2][KSMP];   // 4KB
    __shared__ float A1s[2][HID], b2s[HID], w3s[HID];
    __shared__ float2 sumIE[2];
    __shared__ float bp3s;

    int blk = blockIdx.x;                            // 2048 blocks
    int b   = blk >> 10;                             // / (NPTS/2)
    int n0  = (blk & 1023) * 2;
    int bn  = b*NPTS + n0;
    int t   = threadIdx.x;                           // t = k

    for (int q = t; q < HID*HID; q += 256) W2s[q] = g_W2T[q];
    if (t < 2*HID) A1s[t >> 5][t & 31] = g_A1[bn*HID + t];
    if (t < HID) { b2s[t] = g_bias2[t]; w3s[t] = w_p3[t]; }
    if (t == 0) bp3s = b_p3[0];
    float ne = g_nek[b*KSMP + t];
    __syncthreads();

    // h1 for both points, packed in pairs; B1T column loaded once, used twice
    u64 h1a[HID/2], h1b[HID/2];
    #pragma unroll
    for (int i2 = 0; i2 < HID/2; i2++) {
        float blo = g_B1T[(b*HID + 2*i2    )*KSMP + t];
        float bhi = g_B1T[(b*HID + 2*i2 + 1)*KSMP + t];
        h1a[i2] = pack2(fmaxf(A1s[0][2*i2] + blo, 0.f), fmaxf(A1s[0][2*i2+1] + bhi, 0.f));
        h1b[i2] = pack2(fmaxf(A1s[1][2*i2] + blo, 0.f), fmaxf(A1s[1][2*i2+1] + bhi, 0.f));
    }

    // layer 2 (32x32, f32x2) + layer 3 (32->1) — each W LDS.128 feeds 4 fma2
    float accA = 0.f, accB = 0.f;
    #pragma unroll
    for (int j = 0; j < HID; j++) {
        const ulonglong2* wp = reinterpret_cast<const ulonglong2*>(&W2s[j*HID]);
        u64 za = pack2(b2s[j], 0.f);
        u64 zb = za;
        #pragma unroll
        for (int q = 0; q < 8; q++) {
            ulonglong2 w = wp[q];                    // broadcast LDS.128
            za = fma2(h1a[2*q],     w.x, za);
            za = fma2(h1a[2*q + 1], w.y, za);
            zb = fma2(h1b[2*q],     w.x, zb);
            zb = fma2(h1b[2*q + 1], w.y, zb);
        }
        float l, h;
        unpack2(za, l, h); accA = fmaf(fmaxf(l + h, 0.f), w3s[j], accA);
        unpack2(zb, l, h); accB = fmaf(fmaxf(l + h, 0.f), w3s[j], accB);
    }
    float Pa = 1.f / (1.f + expf(-(accA + bp3s)));
    float Pb = 1.f / (1.f + expf(-(accB + bp3s)));
    wiwe[0][t] = make_float2(Pa * ne, (1.f - Pa) * ne);
    wiwe[1][t] = make_float2(Pb * ne, (1.f - Pb) * ne);
    __syncthreads();

    // warps 0/1: scalar sums of wi/we per point
    if (t < 64) {
        int n = t >> 5, lane = t & 31;
        float si = 0.f, se = 0.f;
        #pragma unroll
        for (int kk = lane; kk < KSMP; kk += 32) {
            float2 v = wiwe[n][kk];
            si += v.x; se += v.y;
        }
        si = warpsum(si); se = warpsum(se);
        if (lane == 0) sumIE[n] = make_float2(si, se);
    }

    // weighted sums over tf: quarter q of k, channel c; tf LDG shared by points
    {
        int c = t & 63, q = t >> 6;
        u64 accа = 0ULL, accb = 0ULL;
        const float* tfb = g_tf + b*KSMP*CH;
        const u64* wv0 = reinterpret_cast<const u64*>(wiwe[0]);
        const u64* wv1 = reinterpret_cast<const u64*>(wiwe[1]);
        #pragma unroll 4
        for (int kk = q*64; kk < q*64 + 64; kk++) {
            float tfv = tfb[kk*CH + c];
            u64 t2 = pack2(tfv, tfv);
            accа = fma2(t2, wv0[kk], accа);
            accb = fma2(t2, wv1[kk], accb);
        }
        float pi, pe;
        unpack2(accа, pi, pe); part[0][t] = make_float2(pi, pe);
        unpack2(accb, pi, pe); part[1][t] = make_float2(pi, pe);
    }
    __syncthreads();

    if (t < 2*CH) {
        int n = t >> 6, c = t & 63;
        float2 p0 = part[n][c], p1 = part[n][64 + c], p2 = part[n][128 + c], p3 = part[n][192 + c];
        float si = p0.x + p1.x + p2.x + p3.x;
        float se = p0.y + p1.y + p2.y + p3.y;
        float2 s = sumIE[n];
        g_xintra[(bn + n)*CH + c] = si / s.x;
        g_xinter[(bn + n)*CH + c] = se / s.y;
    }
}

// ---------------- dense: out = input @ (Weff[0:64]+Weff[192:256]) + beff ----
__global__ void __launch_bounds__(256) dense_kernel(const float* input, float* out) {
    __shared__ float X[CH*65];
    __shared__ __align__(16) float Wl[CH*CH];
    __shared__ float bl[CH];
    int b  = blockIdx.y;
    int v0 = blockIdx.x * 64;
    int t  = threadIdx.x;
    for (int q = t; q < CH*64; q += 256) {
        int c = q >> 6, vl = q & 63;
        X[c*65 + vl] = input[(b*CH + c)*FLATN + v0 + vl];
    }
    for (int q = t; q < CH*CH; q += 256) Wl[q] = g_Weff[q] + g_Weff[3*CH*CH + q];
    if (t < CH) bl[t] = g_beff[t];
    __syncthreads();

    int vl = t & 63, fb = (t >> 6) * 16;
    u64 acc2[8];
    #pragma unroll
    for (int r = 0; r < 8; r++) acc2[r] = pack2(bl[fb + 2*r], bl[fb + 2*r + 1]);
    for (int c = 0; c < CH; c++) {
        float xv = X[c*65 + vl];
        u64 xp = pack2(xv, xv);
        const ulonglong2* wr = reinterpret_cast<const ulonglong2*>(&Wl[c*CH + fb]);
        #pragma unroll
        for (int r = 0; r < 4; r++) {
            ulonglong2 w = wr[r];
            acc2[2*r]   = fma2(xp, w.x, acc2[2*r]);
            acc2[2*r+1] = fma2(xp, w.y, acc2[2*r+1]);
        }
    }
    #pragma unroll
    for (int r = 0; r < 8; r++) {
        float lo, hi; unpack2(acc2[r], lo, hi);
        out[(b*CH + fb + 2*r    )*FLATN + v0 + vl] = lo;
        out[(b*CH + fb + 2*r + 1)*FLATN + v0 + vl] = hi;
    }
}

// ---------------- projection + scatter: 8 points/block, Weff in shared ------
__global__ void __launch_bounds__(256) projscatter_kernel(const int* mask_idx, float* out) {
    __shared__ __align__(16) float Wf[2*CH*CH];    // 32KB: Weff rows [64:192)
    __shared__ float xa[PT*CH], xb[PT*CH];
    __shared__ int vs[PT];
    int blk = blockIdx.x;
    int b   = blk / (NPTS/PT);
    int p0  = (blk % (NPTS/PT)) * PT;
    int t   = threadIdx.x;
    for (int q = t; q < 2*CH*CH; q += 256) Wf[q] = g_Weff[CH*CH + q];
    for (int q = t; q < PT*CH; q += 256) {
        xa[q] = g_xintra[(b*NPTS + p0)*CH + q];
        xb[q] = g_xinter[(b*NPTS + p0)*CH + q];
    }
    if (t < PT) vs[t] = mask_idx[b*NPTS + p0 + t];
    __syncthreads();
    for (int idx = t; idx < PT*CH; idx += 256) {
        int n = idx >> 6, f = idx & 63;
        float acc = 0.f;
        #pragma unroll 8
        for (int j = 0; j < CH; j++) {
            acc = fmaf(xa[n*CH + j], Wf[j*CH + f], acc);
            acc = fmaf(xb[n*CH + j], Wf[CH*CH + j*CH + f], acc);
        }
        out[(b*CH + f)*FLATN + vs[n]] += acc;
    }
}

// -----------------------------------------------------------------------------
extern "C" void kernel_launch(void* const* d_in, const int* in_sizes, int n_in,
                              void* d_out, int out_size) {
    const float* input    = (const float*)d_in[0];
    const int*   mask_idx = (const int*)  d_in[1];
    const float* w_ne1 = (const float*)d_in[2];
    const float* b_ne1 = (const float*)d_in[3];
    const float* g_ne  = (const float*)d_in[4];
    const float* be_ne = (const float*)d_in[5];
    const float* w_ne2 = (const float*)d_in[6];
    const float* b_ne2 = (const float*)d_in[7];
    const float* w_p1  = (const float*)d_in[8];
    const float* b_p1  = (const float*)d_in[9];
    const float* g_p1  = (const float*)d_in[10];
    const float* be_p1 = (const float*)d_in[11];
    const float* w_p2  = (const float*)d_in[12];
    const float* b_p2  = (const float*)d_in[13];
    const float* g_p2  = (const float*)d_in[14];
    const float* be_p2 = (const float*)d_in[15];
    const float* w_p3  = (const float*)d_in[16];
    const float* b_p3  = (const float*)d_in[17];
    const float* w_r1  = (const float*)d_in[18];
    const float* b_r1  = (const float*)d_in[19];
    const float* w_r2  = (const float*)d_in[20];
    const float* b_r2  = (const float*)d_in[21];
    float* out = (float*)d_out;

    // pair is launch #4 so the harness ncu capture lands on it
    weffprep_kernel<<<4*CH, CH>>>(w_r1, w_r2, b_ne1, g_ne, be_ne,
                                  b_p1, g_p1, be_p1, w_p2, b_p2, g_p2, be_p2,
                                  b_r1, b_r2);
    gxifeat_kernel<<<BSZ*NPTS/PT, 256>>>(input, mask_idx, w_ne1, w_ne2, b_ne2, w_p1);
    samplegather_kernel<<<BSZ*KSMP, 256>>>(w_p1);
    pair_kernel<<<BSZ*NPTS/2, 256>>>(w_p3, b_p3);
    dense_kernel<<<dim3(FLATN/64, BSZ), 256>>>(input, out);
    projscatter_kernel<<<BSZ*NPTS/PT, 256>>>(mask_idx, out);
}

// round 6
// speedup vs baseline: 7.3205x; 1.0235x over previous
#include <cuda_runtime.h>
#include <stdint.h>

#define JAX_PARTITIONABLE 1

#define BSZ   2
#define CH    64
#define FLATN 16384
#define NPTS  2048
#define KSMP  256
#define HID   32
#define PT    8      // points per gxifeat/projscatter block
#define GXIB  (BSZ*NPTS/PT)          // 512 gxifeat blocks
#define DENB  (FLATN/64*BSZ)         // 512 dense blocks

typedef unsigned long long u64;

// ---------------- device scratch ------------------------------------------
__device__ float g_xi    [BSZ*NPTS*CH];
__device__ float g_mpe   [BSZ*NPTS*CH];
__device__ float g_A1    [BSZ*NPTS*HID];
__device__ float g_prob  [BSZ*NPTS];
__device__ float g_logp  [BSZ*NPTS];
__device__ float g_B1T   [BSZ*HID*KSMP];   // [b][i][k], bias1 folded in
__device__ float g_tf    [BSZ*KSMP*CH];
__device__ float g_nek   [BSZ*KSMP];
__device__ float g_xintra[BSZ*NPTS*CH];
__device__ float g_xinter[BSZ*NPTS*CH];
__device__ float g_Weff  [4*CH*CH];        // w_r1 @ w_r2
__device__ float g_beff  [CH];
__device__ float g_s1[HID], g_bias1[HID], g_W2T[HID*HID], g_bias2[HID];
__device__ float g_sne[HID], g_biasne[HID];

// ---------------- helpers ---------------------------------------------------
__device__ __forceinline__ float warpsum(float v) {
    #pragma unroll
    for (int o = 16; o > 0; o >>= 1) v += __shfl_xor_sync(0xffffffffu, v, o);
    return v;
}
__device__ __forceinline__ u64 pack2(float lo, float hi) {
    u64 r; asm("mov.b64 %0, {%1,%2};" : "=l"(r) : "f"(lo), "f"(hi)); return r;
}
__device__ __forceinline__ void unpack2(u64 v, float& lo, float& hi) {
    asm("mov.b64 {%0,%1}, %2;" : "=f"(lo), "=f"(hi) : "l"(v));
}
__device__ __forceinline__ u64 fma2(u64 a, u64 b, u64 c) {
    u64 d; asm("fma.rn.f32x2 %0, %1, %2, %3;" : "=l"(d) : "l"(a), "l"(b), "l"(c)); return d;
}
__device__ __forceinline__ uint32_t rotl32(uint32_t x, int d) {
    return (x << d) | (x >> (32 - d));
}
__device__ __forceinline__ void tf2x32(uint32_t k0, uint32_t k1,
                                       uint32_t x0, uint32_t x1,
                                       uint32_t& o0, uint32_t& o1) {
    uint32_t ks0 = k0, ks1 = k1, ks2 = k0 ^ k1 ^ 0x1BD11BDAu;
    x0 += ks0; x1 += ks1;
#define TF_RND(r) { x0 += x1; x1 = rotl32(x1, r); x1 ^= x0; }
    TF_RND(13) TF_RND(15) TF_RND(26) TF_RND(6)  x0 += ks1; x1 += ks2 + 1u;
    TF_RND(17) TF_RND(29) TF_RND(16) TF_RND(24) x0 += ks2; x1 += ks0 + 2u;
    TF_RND(13) TF_RND(15) TF_RND(26) TF_RND(6)  x0 += ks0; x1 += ks1 + 3u;
    TF_RND(17) TF_RND(29) TF_RND(16) TF_RND(24) x0 += ks1; x1 += ks2 + 4u;
    TF_RND(13) TF_RND(15) TF_RND(26) TF_RND(6)  x0 += ks2; x1 += ks0 + 5u;
#undef TF_RND
    o0 = x0; o1 = x1;
}

// ---------------- weff + prep (fused) ---------------------------------------
__global__ void weffprep_kernel(const float* w_r1, const float* w_r2,
                                const float* b_ne1, const float* g_ne, const float* be_ne,
                                const float* b_p1,  const float* g_p1, const float* be_p1,
                                const float* w_p2,  const float* b_p2, const float* g_p2,
                                const float* be_p2, const float* b_r1, const float* b_r2) {
    __shared__ float row[2*CH];
    int c = blockIdx.x, f = threadIdx.x;
    row[f]      = w_r1[c*2*CH + f];
    row[f + CH] = w_r1[c*2*CH + f + CH];
    __syncthreads();
    float acc = 0.f;
    #pragma unroll 8
    for (int m = 0; m < 2*CH; m++) acc = fmaf(row[m], w_r2[m*CH + f], acc);
    g_Weff[c*CH + f] = acc;

    if (blockIdx.x == 0) {
        int t = threadIdx.x;
        float inv = 1.0f / sqrtf(1.0f + 1e-5f);
        if (t < HID) {
            float sne = g_ne[t] * inv;
            g_sne[t] = sne;
            g_biasne[t] = fmaf(b_ne1[t], sne, be_ne[t]);
            float s1 = g_p1[t] * inv;
            g_s1[t] = s1;
            g_bias1[t] = fmaf(b_p1[t], s1, be_p1[t]);
            float s2 = g_p2[t] * inv;
            g_bias2[t] = fmaf(b_p2[t], s2, be_p2[t]);
            for (int i = 0; i < HID; i++)
                g_W2T[t*HID + i] = w_p2[i*HID + t] * s2;
        }
        if (t < CH) {
            float a2 = b_r2[t];
            for (int m = 0; m < 2*CH; m++) a2 = fmaf(b_r1[m], w_r2[m*CH + t], a2);
            g_beff[t] = a2;
        }
    }
}

// ---------------- fused gxifeat + dense (heterogeneous blocks) --------------
// blocks [0, GXIB): gather+PE+ne-prob+A1 (8 points each)
// blocks [GXIB, GXIB+DENB): dense out = input @ Win + beff (independent path)
__global__ void __launch_bounds__(256) gxidense_kernel(
        const float* input, const int* mask_idx,
        const float* w_ne1, const float* w_ne2, const float* b_ne2,
        const float* w_p1, float* out) {
    __shared__ float X[CH*65];                   // dense: 16.25KB / gxi: reuse head
    __shared__ __align__(16) float Wl[CH*CH];    // dense: 16KB
    __shared__ float bl[CH];
    int t = threadIdx.x;

    if (blockIdx.x < GXIB) {
        // ---- gxifeat path ----
        float* xs = X;                           // PT*CH = 512 floats
        __shared__ int   vs[PT];
        __shared__ float divs[HID];
        int b  = blockIdx.x / (NPTS/PT);
        int p0 = (blockIdx.x % (NPTS/PT)) * PT;
        const float kc = -0.1439115683121279f;   // -ln(10000)/64
        if (t < PT) vs[t] = mask_idx[b*NPTS + p0 + t];
        if (t < HID) divs[t] = expf((float)(2*t) * kc);
        __syncthreads();
        for (int idx = t; idx < PT*CH; idx += 256) {
            int p = idx >> 6, c = idx & 63;
            int v = vs[p];
            float ang = (float)v * divs[c >> 1];
            float pe  = (c & 1) ? cosf(ang) : sinf(ang);
            float xi  = input[(b*CH + c)*FLATN + v] + pe;
            int bn = b*NPTS + p0 + p;
            g_xi [bn*CH + c] = xi;
            g_mpe[bn*CH + c] = pe;
            xs[p*CH + c] = xi;
        }
        __syncthreads();
        int w = t >> 5, j = t & 31;              // warp w -> point w
        float dn = 0.f, dp = 0.f;
        #pragma unroll
        for (int c = 0; c < CH; c++) {
            float x = xs[w*CH + c];
            dn = fmaf(x, w_ne1[c*HID + j], dn);
            dp = fmaf(x, w_p1 [c*HID + j], dp);
        }
        int bn = b*NPTS + p0 + w;
        g_A1[bn*HID + j] = dp * g_s1[j];
        float h = fmaxf(fmaf(dn, g_sne[j], g_biasne[j]), 0.f);
        float s = warpsum(h * w_ne2[j]);
        if (j == 0) {
            float logit = s + b_ne2[0];
            float p = 1.f / (1.f + expf(-logit));
            g_prob[bn] = p;
            g_logp[bn] = logf(p);
        }
    } else {
        // ---- dense path ----
        int d  = blockIdx.x - GXIB;
        int b  = d >> 8;
        int v0 = (d & 255) * 64;
        for (int q = t; q < CH*64; q += 256) {
            int c = q >> 6, vl = q & 63;
            X[c*65 + vl] = input[(b*CH + c)*FLATN + v0 + vl];
        }
        for (int q = t; q < CH*CH; q += 256) Wl[q] = g_Weff[q] + g_Weff[3*CH*CH + q];
        if (t < CH) bl[t] = g_beff[t];
        __syncthreads();

        int vl = t & 63, fb = (t >> 6) * 16;
        u64 acc2[8];
        #pragma unroll
        for (int r = 0; r < 8; r++) acc2[r] = pack2(bl[fb + 2*r], bl[fb + 2*r + 1]);
        for (int c = 0; c < CH; c++) {
            float xv = X[c*65 + vl];
            u64 xp = pack2(xv, xv);
            const ulonglong2* wr = reinterpret_cast<const ulonglong2*>(&Wl[c*CH + fb]);
            #pragma unroll
            for (int r = 0; r < 4; r++) {
                ulonglong2 w = wr[r];
                acc2[2*r]   = fma2(xp, w.x, acc2[2*r]);
                acc2[2*r+1] = fma2(xp, w.y, acc2[2*r+1]);
            }
        }
        #pragma unroll
        for (int r = 0; r < 8; r++) {
            float lo, hi; unpack2(acc2[r], lo, hi);
            out[(b*CH + fb + 2*r    )*FLATN + v0 + vl] = lo;
            out[(b*CH + fb + 2*r + 1)*FLATN + v0 + vl] = hi;
        }
    }
}

// ---------------- gumbel-max sampling + gather of sampled row ---------------
__global__ void __launch_bounds__(256) samplegather_kernel(const float* w_p1) {
    int bi = blockIdx.x;
    int b  = bi >> 8;
    int i  = bi & 255;
    int t  = threadIdx.x;

    uint32_t kb0, kb1;
#if JAX_PARTITIONABLE
    tf2x32(0u, 42u, 0u, (uint32_t)b, kb0, kb1);
#else
    uint32_t a0, a1, c0, c1;
    tf2x32(0u, 42u, 0u, 2u, a0, a1);
    tf2x32(0u, 42u, 1u, 3u, c0, c1);
    if (b == 0) { kb0 = a0; kb1 = c0; } else { kb0 = a1; kb1 = c1; }
#endif

    const float TINY = 1.1754943508222875e-38f;
    float best = -3.402823466e38f;
    int   bidx = 0x7fffffff;
    for (int n = t; n < NPTS; n += 256) {
        uint32_t m = (uint32_t)(i*NPTS + n);
        uint32_t o0, o1, bits;
#if JAX_PARTITIONABLE
        tf2x32(kb0, kb1, 0u, m, o0, o1);
        bits = o0 ^ o1;
#else
        const uint32_t half = (KSMP * NPTS) / 2;
        if (m < half) { tf2x32(kb0, kb1, m, m + half, o0, o1); bits = o0; }
        else          { tf2x32(kb0, kb1, m - half, m, o0, o1); bits = o1; }
#endif
        float f = __uint_as_float((bits >> 9) | 0x3f800000u) - 1.0f;
        float u = fmaxf(f + TINY, TINY);
        float g = -logf(-logf(u));
        float val = g + g_logp[b*NPTS + n];
        if (val > best) { best = val; bidx = n; }
    }
    __shared__ float sv[256];
    __shared__ int   si[256];
    __shared__ float ms[CH];
    sv[t] = best; si[t] = bidx;
    __syncthreads();
    for (int s = 128; s > 0; s >>= 1) {
        if (t < s) {
            if (sv[t+s] > sv[t] || (sv[t+s] == sv[t] && si[t+s] < si[t])) {
                sv[t] = sv[t+s]; si[t] = si[t+s];
            }
        }
        __syncthreads();
    }
    int n = si[0];
    int src = (b*NPTS + n)*CH;
    if (t < CH) {
        ms[t] = g_mpe[src + t];
        g_tf[bi*CH + t] = g_xi[src + t];
    }
    __syncthreads();
    if (t < HID) {
        float d = 0.f;
        #pragma unroll
        for (int c = 0; c < CH; c++) d = fmaf(ms[c], w_p1[c*HID + t], d);
        g_B1T[(b*HID + t)*KSMP + i] = fmaf(d, g_s1[t], g_bias1[t]);  // bias1 folded
    }
    if (t == 0) g_nek[bi] = g_prob[b*NPTS + n];
}

// ---------------- heavy pairwise kernel: 2 points per block, shared W2 LDS --
__global__ void __launch_bounds__(256) pair_kernel(const float* w_p3, const float* b_p3) {
    __shared__ __align__(16) float  W2s[HID*HID];    // 4KB
    __shared__ __align__(16) float2 wiwe[2][KSMP];   // 4KB
    __shared__ __align__(16) float2 part[2][KSMP];   // 4KB
    __shared__ float A1s[2][HID], b2s[HID], w3s[HID];
    __shared__ float2 sumIE[2];
    __shared__ float bp3s;

    int blk = blockIdx.x;                            // 2048 blocks
    int b   = blk >> 10;                             // / (NPTS/2)
    int n0  = (blk & 1023) * 2;
    int bn  = b*NPTS + n0;
    int t   = threadIdx.x;                           // t = k

    for (int q = t; q < HID*HID; q += 256) W2s[q] = g_W2T[q];
    if (t < 2*HID) A1s[t >> 5][t & 31] = g_A1[bn*HID + t];
    if (t < HID) { b2s[t] = g_bias2[t]; w3s[t] = w_p3[t]; }
    if (t == 0) bp3s = b_p3[0];
    float ne = g_nek[b*KSMP + t];
    __syncthreads();

    // h1 for both points, packed in pairs; B1T column loaded once, used twice
    u64 h1a[HID/2], h1b[HID/2];
    #pragma unroll
    for (int i2 = 0; i2 < HID/2; i2++) {
        float blo = g_B1T[(b*HID + 2*i2    )*KSMP + t];
        float bhi = g_B1T[(b*HID + 2*i2 + 1)*KSMP + t];
        h1a[i2] = pack2(fmaxf(A1s[0][2*i2] + blo, 0.f), fmaxf(A1s[0][2*i2+1] + bhi, 0.f));
        h1b[i2] = pack2(fmaxf(A1s[1][2*i2] + blo, 0.f), fmaxf(A1s[1][2*i2+1] + bhi, 0.f));
    }

    // layer 2 (32x32, f32x2) + layer 3 (32->1) — each W LDS.128 feeds 4 fma2
    // unroll 4 keeps hot-loop SASS within L0 I$ (full unroll = ~24KB, misses)
    float accA = 0.f, accB = 0.f;
    #pragma unroll 4
    for (int j = 0; j < HID; j++) {
        const ulonglong2* wp = reinterpret_cast<const ulonglong2*>(&W2s[j*HID]);
        u64 za = pack2(b2s[j], 0.f);
        u64 zb = za;
        #pragma unroll
        for (int q = 0; q < 8; q++) {
            ulonglong2 w = wp[q];                    // broadcast LDS.128
            za = fma2(h1a[2*q],     w.x, za);
            za = fma2(h1a[2*q + 1], w.y, za);
            zb = fma2(h1b[2*q],     w.x, zb);
            zb = fma2(h1b[2*q + 1], w.y, zb);
        }
        float l, h;
        unpack2(za, l, h); accA = fmaf(fmaxf(l + h, 0.f), w3s[j], accA);
        unpack2(zb, l, h); accB = fmaf(fmaxf(l + h, 0.f), w3s[j], accB);
    }
    float Pa = 1.f / (1.f + expf(-(accA + bp3s)));
    float Pb = 1.f / (1.f + expf(-(accB + bp3s)));
    wiwe[0][t] = make_float2(Pa * ne, (1.f - Pa) * ne);
    wiwe[1][t] = make_float2(Pb * ne, (1.f - Pb) * ne);
    __syncthreads();

    // warps 0/1: scalar sums of wi/we per point
    if (t < 64) {
        int n = t >> 5, lane = t & 31;
        float si = 0.f, se = 0.f;
        #pragma unroll
        for (int kk = lane; kk < KSMP; kk += 32) {
            float2 v = wiwe[n][kk];
            si += v.x; se += v.y;
        }
        si = warpsum(si); se = warpsum(se);
        if (lane == 0) sumIE[n] = make_float2(si, se);
    }

    // weighted sums over tf: quarter q of k, channel c; tf LDG shared by points
    {
        int c = t & 63, q = t >> 6;
        u64 accA2 = 0ULL, accB2 = 0ULL;
        const float* tfb = g_tf + b*KSMP*CH;
        const u64* wv0 = reinterpret_cast<const u64*>(wiwe[0]);
        const u64* wv1 = reinterpret_cast<const u64*>(wiwe[1]);
        #pragma unroll 4
        for (int kk = q*64; kk < q*64 + 64; kk++) {
            float tfv = tfb[kk*CH + c];
            u64 t2 = pack2(tfv, tfv);
            accA2 = fma2(t2, wv0[kk], accA2);
            accB2 = fma2(t2, wv1[kk], accB2);
        }
        float pi, pe;
        unpack2(accA2, pi, pe); part[0][t] = make_float2(pi, pe);
        unpack2(accB2, pi, pe); part[1][t] = make_float2(pi, pe);
    }
    __syncthreads();

    if (t < 2*CH) {
        int n = t >> 6, c = t & 63;
        float2 p0 = part[n][c], p1 = part[n][64 + c], p2 = part[n][128 + c], p3 = part[n][192 + c];
        float si = p0.x + p1.x + p2.x + p3.x;
        float se = p0.y + p1.y + p2.y + p3.y;
        float2 s = sumIE[n];
        g_xintra[(bn + n)*CH + c] = si / s.x;
        g_xinter[(bn + n)*CH + c] = se / s.y;
    }
}

// ---------------- projection + scatter: 8 points/block, Weff in shared ------
__global__ void __launch_bounds__(256) projscatter_kernel(const int* mask_idx, float* out) {
    __shared__ __align__(16) float Wf[2*CH*CH];    // 32KB: Weff rows [64:192)
    __shared__ float xa[PT*CH], xb[PT*CH];
    __shared__ int vs[PT];
    int blk = blockIdx.x;
    int b   = blk / (NPTS/PT);
    int p0  = (blk % (NPTS/PT)) * PT;
    int t   = threadIdx.x;
    for (int q = t; q < 2*CH*CH; q += 256) Wf[q] = g_Weff[CH*CH + q];
    for (int q = t; q < PT*CH; q += 256) {
        xa[q] = g_xintra[(b*NPTS + p0)*CH + q];
        xb[q] = g_xinter[(b*NPTS + p0)*CH + q];
    }
    if (t < PT) vs[t] = mask_idx[b*NPTS + p0 + t];
    __syncthreads();
    for (int idx = t; idx < PT*CH; idx += 256) {
        int n = idx >> 6, f = idx & 63;
        float acc = 0.f;
        #pragma unroll 8
        for (int j = 0; j < CH; j++) {
            acc = fmaf(xa[n*CH + j], Wf[j*CH + f], acc);
            acc = fmaf(xb[n*CH + j], Wf[CH*CH + j*CH + f], acc);
        }
        out[(b*CH + f)*FLATN + vs[n]] += acc;
    }
}

// -----------------------------------------------------------------------------
extern "C" void kernel_launch(void* const* d_in, const int* in_sizes, int n_in,
                              void* d_out, int out_size) {
    const float* input    = (const float*)d_in[0];
    const int*   mask_idx = (const int*)  d_in[1];
    const float* w_ne1 = (const float*)d_in[2];
    const float* b_ne1 = (const float*)d_in[3];
    const float* g_ne  = (const float*)d_in[4];
    const float* be_ne = (const float*)d_in[5];
    const float* w_ne2 = (const float*)d_in[6];
    const float* b_ne2 = (const float*)d_in[7];
    const float* w_p1  = (const float*)d_in[8];
    const float* b_p1  = (const float*)d_in[9];
    const float* g_p1  = (const float*)d_in[10];
    const float* be_p1 = (const float*)d_in[11];
    const float* w_p2  = (const float*)d_in[12];
    const float* b_p2  = (const float*)d_in[13];
    const float* g_p2  = (const float*)d_in[14];
    const float* be_p2 = (const float*)d_in[15];
    const float* w_p3  = (const float*)d_in[16];
    const float* b_p3  = (const float*)d_in[17];
    const float* w_r1  = (const float*)d_in[18];
    const float* b_r1  = (const float*)d_in[19];
    const float* w_r2  = (const float*)d_in[20];
    const float* b_r2  = (const float*)d_in[21];
    float* out = (float*)d_out;

    weffprep_kernel<<<4*CH, CH>>>(w_r1, w_r2, b_ne1, g_ne, be_ne,
                                  b_p1, g_p1, be_p1, w_p2, b_p2, g_p2, be_p2,
                                  b_r1, b_r2);
    gxidense_kernel<<<GXIB + DENB, 256>>>(input, mask_idx, w_ne1, w_ne2, b_ne2,
                                          w_p1, out);
    samplegather_kernel<<<BSZ*KSMP, 256>>>(w_p1);
    pair_kernel<<<BSZ*NPTS/2, 256>>>(w_p3, b_p3);   // launch #4 -> ncu target
    projscatter_kernel<<<BSZ*NPTS/PT, 256>>>(mask_idx, out);
}

// round 7
// speedup vs baseline: 7.6121x; 1.0398x over previous
#include <cuda_runtime.h>
#include <stdint.h>

#define JAX_PARTITIONABLE 1

#define BSZ   2
#define CH    64
#define FLATN 16384
#define NPTS  2048
#define KSMP  256
#define HID   32
#define PT    8
#define GXIB  (BSZ*NPTS/PT)          // 512 gxifeat blocks
#define DENB  (FLATN/64*BSZ)         // 512 dense blocks
#define GUMB  (BSZ*KSMP)             // 512 gumbel-table blocks

typedef unsigned long long u64;

// ---------------- device scratch ------------------------------------------
__device__ float g_xi    [BSZ*NPTS*CH];
__device__ float g_mpe   [BSZ*NPTS*CH];
__device__ float g_A1    [BSZ*NPTS*HID];
__device__ float g_prob  [BSZ*NPTS];
__device__ float g_logp  [BSZ*NPTS];
__device__ float g_B1T   [BSZ*HID*KSMP];     // [b][i][k], bias1 folded in
__device__ float g_tf    [BSZ*KSMP*CH];
__device__ float g_nek   [BSZ*KSMP];
__device__ float g_gum   [BSZ*KSMP*NPTS];    // gumbel noise table [bi][n]
__device__ float g_Weff  [4*CH*CH];          // w_r1 @ w_r2
__device__ float g_beff  [CH];
__device__ float g_s1[HID], g_bias1[HID], g_W2T[HID*HID], g_bias2[HID];
__device__ float g_sne[HID], g_biasne[HID];

// ---------------- helpers ---------------------------------------------------
__device__ __forceinline__ float warpsum(float v) {
    #pragma unroll
    for (int o = 16; o > 0; o >>= 1) v += __shfl_xor_sync(0xffffffffu, v, o);
    return v;
}
__device__ __forceinline__ u64 pack2(float lo, float hi) {
    u64 r; asm("mov.b64 %0, {%1,%2};" : "=l"(r) : "f"(lo), "f"(hi)); return r;
}
__device__ __forceinline__ void unpack2(u64 v, float& lo, float& hi) {
    asm("mov.b64 {%0,%1}, %2;" : "=f"(lo), "=f"(hi) : "l"(v));
}
__device__ __forceinline__ u64 fma2(u64 a, u64 b, u64 c) {
    u64 d; asm("fma.rn.f32x2 %0, %1, %2, %3;" : "=l"(d) : "l"(a), "l"(b), "l"(c)); return d;
}
__device__ __forceinline__ uint32_t rotl32(uint32_t x, int d) {
    return (x << d) | (x >> (32 - d));
}
__device__ __forceinline__ void tf2x32(uint32_t k0, uint32_t k1,
                                       uint32_t x0, uint32_t x1,
                                       uint32_t& o0, uint32_t& o1) {
    uint32_t ks0 = k0, ks1 = k1, ks2 = k0 ^ k1 ^ 0x1BD11BDAu;
    x0 += ks0; x1 += ks1;
#define TF_RND(r) { x0 += x1; x1 = rotl32(x1, r); x1 ^= x0; }
    TF_RND(13) TF_RND(15) TF_RND(26) TF_RND(6)  x0 += ks1; x1 += ks2 + 1u;
    TF_RND(17) TF_RND(29) TF_RND(16) TF_RND(24) x0 += ks2; x1 += ks0 + 2u;
    TF_RND(13) TF_RND(15) TF_RND(26) TF_RND(6)  x0 += ks0; x1 += ks1 + 3u;
    TF_RND(17) TF_RND(29) TF_RND(16) TF_RND(24) x0 += ks1; x1 += ks2 + 4u;
    TF_RND(13) TF_RND(15) TF_RND(26) TF_RND(6)  x0 += ks2; x1 += ks0 + 5u;
#undef TF_RND
    o0 = x0; o1 = x1;
}
__device__ __forceinline__ void batch_keys(int b, uint32_t& kb0, uint32_t& kb1) {
#if JAX_PARTITIONABLE
    tf2x32(0u, 42u, 0u, (uint32_t)b, kb0, kb1);
#else
    uint32_t a0, a1, c0, c1;
    tf2x32(0u, 42u, 0u, 2u, a0, a1);
    tf2x32(0u, 42u, 1u, 3u, c0, c1);
    if (b == 0) { kb0 = a0; kb1 = c0; } else { kb0 = a1; kb1 = c1; }
#endif
}
__device__ __forceinline__ float gumbel_of(uint32_t kb0, uint32_t kb1, uint32_t m) {
    uint32_t o0, o1, bits;
#if JAX_PARTITIONABLE
    tf2x32(kb0, kb1, 0u, m, o0, o1);
    bits = o0 ^ o1;
#else
    const uint32_t half = (KSMP * NPTS) / 2;
    if (m < half) { tf2x32(kb0, kb1, m, m + half, o0, o1); bits = o0; }
    else          { tf2x32(kb0, kb1, m - half, m, o0, o1); bits = o1; }
#endif
    const float TINY = 1.1754943508222875e-38f;
    float f = __uint_as_float((bits >> 9) | 0x3f800000u) - 1.0f;
    float u = fmaxf(f + TINY, TINY);
    return -logf(-logf(u));
}

// ---------------- weff + prep (fused) ---------------------------------------
__global__ void weffprep_kernel(const float* w_r1, const float* w_r2,
                                const float* b_ne1, const float* g_ne, const float* be_ne,
                                const float* b_p1,  const float* g_p1, const float* be_p1,
                                const float* w_p2,  const float* b_p2, const float* g_p2,
                                const float* be_p2, const float* b_r1, const float* b_r2) {
    __shared__ float row[2*CH];
    int c = blockIdx.x, f = threadIdx.x;
    row[f]      = w_r1[c*2*CH + f];
    row[f + CH] = w_r1[c*2*CH + f + CH];
    __syncthreads();
    float acc = 0.f;
    #pragma unroll 8
    for (int m = 0; m < 2*CH; m++) acc = fmaf(row[m], w_r2[m*CH + f], acc);
    g_Weff[c*CH + f] = acc;

    if (blockIdx.x == 0) {
        int t = threadIdx.x;
        float inv = 1.0f / sqrtf(1.0f + 1e-5f);
        if (t < HID) {
            float sne = g_ne[t] * inv;
            g_sne[t] = sne;
            g_biasne[t] = fmaf(b_ne1[t], sne, be_ne[t]);
            float s1 = g_p1[t] * inv;
            g_s1[t] = s1;
            g_bias1[t] = fmaf(b_p1[t], s1, be_p1[t]);
            float s2 = g_p2[t] * inv;
            g_bias2[t] = fmaf(b_p2[t], s2, be_p2[t]);
            for (int i = 0; i < HID; i++)
                g_W2T[t*HID + i] = w_p2[i*HID + t] * s2;
        }
        if (t < CH) {
            float a2 = b_r2[t];
            for (int m = 0; m < 2*CH; m++) a2 = fmaf(b_r1[m], w_r2[m*CH + t], a2);
            g_beff[t] = a2;
        }
    }
}

// ---------------- fused gxifeat + dense + gumbel-table ----------------------
// blocks [0, GXIB): gather+PE+ne-prob+A1 (8 points each)
// blocks [GXIB, GXIB+DENB): dense out = input @ Win + beff
// blocks [GXIB+DENB, +GUMB): gumbel noise table (data-independent)
__global__ void __launch_bounds__(256) gxidense_kernel(
        const float* input, const int* mask_idx,
        const float* w_ne1, const float* w_ne2, const float* b_ne2,
        const float* w_p1, float* out) {
    __shared__ float X[CH*65];
    __shared__ __align__(16) float Wl[CH*CH];
    __shared__ float bl[CH];
    int t = threadIdx.x;

    if (blockIdx.x < GXIB) {
        // ---- gxifeat path ----
        float* xs = X;
        __shared__ int   vs[PT];
        __shared__ float divs[HID];
        int b  = blockIdx.x / (NPTS/PT);
        int p0 = (blockIdx.x % (NPTS/PT)) * PT;
        const float kc = -0.1439115683121279f;   // -ln(10000)/64
        if (t < PT) vs[t] = mask_idx[b*NPTS + p0 + t];
        if (t < HID) divs[t] = expf((float)(2*t) * kc);
        __syncthreads();
        for (int idx = t; idx < PT*CH; idx += 256) {
            int p = idx >> 6, c = idx & 63;
            int v = vs[p];
            float ang = (float)v * divs[c >> 1];
            float pe  = (c & 1) ? cosf(ang) : sinf(ang);
            float xi  = input[(b*CH + c)*FLATN + v] + pe;
            int bn = b*NPTS + p0 + p;
            g_xi [bn*CH + c] = xi;
            g_mpe[bn*CH + c] = pe;
            xs[p*CH + c] = xi;
        }
        __syncthreads();
        int w = t >> 5, j = t & 31;
        float dn = 0.f, dp = 0.f;
        #pragma unroll
        for (int c = 0; c < CH; c++) {
            float x = xs[w*CH + c];
            dn = fmaf(x, w_ne1[c*HID + j], dn);
            dp = fmaf(x, w_p1 [c*HID + j], dp);
        }
        int bn = b*NPTS + p0 + w;
        g_A1[bn*HID + j] = dp * g_s1[j];
        float h = fmaxf(fmaf(dn, g_sne[j], g_biasne[j]), 0.f);
        float s = warpsum(h * w_ne2[j]);
        if (j == 0) {
            float logit = s + b_ne2[0];
            float p = 1.f / (1.f + expf(-logit));
            g_prob[bn] = p;
            g_logp[bn] = logf(p);
        }
    } else if (blockIdx.x < GXIB + DENB) {
        // ---- dense path ----
        int d  = blockIdx.x - GXIB;
        int b  = d >> 8;
        int v0 = (d & 255) * 64;
        for (int q = t; q < CH*64; q += 256) {
            int c = q >> 6, vl = q & 63;
            X[c*65 + vl] = input[(b*CH + c)*FLATN + v0 + vl];
        }
        for (int q = t; q < CH*CH; q += 256) Wl[q] = g_Weff[q] + g_Weff[3*CH*CH + q];
        if (t < CH) bl[t] = g_beff[t];
        __syncthreads();

        int vl = t & 63, fb = (t >> 6) * 16;
        u64 acc2[8];
        #pragma unroll
        for (int r = 0; r < 8; r++) acc2[r] = pack2(bl[fb + 2*r], bl[fb + 2*r + 1]);
        for (int c = 0; c < CH; c++) {
            float xv = X[c*65 + vl];
            u64 xp = pack2(xv, xv);
            const ulonglong2* wr = reinterpret_cast<const ulonglong2*>(&Wl[c*CH + fb]);
            #pragma unroll
            for (int r = 0; r < 4; r++) {
                ulonglong2 w = wr[r];
                acc2[2*r]   = fma2(xp, w.x, acc2[2*r]);
                acc2[2*r+1] = fma2(xp, w.y, acc2[2*r+1]);
            }
        }
        #pragma unroll
        for (int r = 0; r < 8; r++) {
            float lo, hi; unpack2(acc2[r], lo, hi);
            out[(b*CH + fb + 2*r    )*FLATN + v0 + vl] = lo;
            out[(b*CH + fb + 2*r + 1)*FLATN + v0 + vl] = hi;
        }
    } else {
        // ---- gumbel table path: one block per (b,i) sample row ----
        int bi = blockIdx.x - (GXIB + DENB);
        int b  = bi >> 8;
        int i  = bi & 255;
        uint32_t kb0, kb1;
        batch_keys(b, kb0, kb1);
        int n0 = t * 8;
        float g[8];
        #pragma unroll
        for (int r = 0; r < 8; r++)
            g[r] = gumbel_of(kb0, kb1, (uint32_t)(i*NPTS + n0 + r));
        float4* dst = reinterpret_cast<float4*>(&g_gum[bi*NPTS + n0]);
        dst[0] = make_float4(g[0], g[1], g[2], g[3]);
        dst[1] = make_float4(g[4], g[5], g[6], g[7]);
    }
}

// ---------------- sampling: scan gumbel table + logp, argmax, gather --------
__global__ void __launch_bounds__(256) samplegather_kernel(const float* w_p1) {
    int bi = blockIdx.x;
    int b  = bi >> 8;
    int t  = threadIdx.x;

    float best = -3.402823466e38f;
    int   bidx = 0x7fffffff;
    {
        const float4* gv = reinterpret_cast<const float4*>(&g_gum[bi*NPTS]);
        const float4* lp = reinterpret_cast<const float4*>(&g_logp[b*NPTS]);
        int n0 = t * 8;
        #pragma unroll
        for (int r = 0; r < 2; r++) {
            float4 g = gv[t*2 + r];
            float4 l = lp[t*2 + r];
            float v0 = g.x + l.x, v1 = g.y + l.y, v2 = g.z + l.z, v3 = g.w + l.w;
            int nb = n0 + r*4;
            if (v0 > best) { best = v0; bidx = nb; }
            if (v1 > best) { best = v1; bidx = nb + 1; }
            if (v2 > best) { best = v2; bidx = nb + 2; }
            if (v3 > best) { best = v3; bidx = nb + 3; }
        }
    }
    __shared__ float sv[256];
    __shared__ int   si[256];
    __shared__ float ms[CH];
    sv[t] = best; si[t] = bidx;
    __syncthreads();
    for (int s = 128; s > 0; s >>= 1) {
        if (t < s) {
            if (sv[t+s] > sv[t] || (sv[t+s] == sv[t] && si[t+s] < si[t])) {
                sv[t] = sv[t+s]; si[t] = si[t+s];
            }
        }
        __syncthreads();
    }
    int n = si[0];
    int src = (b*NPTS + n)*CH;
    if (t < CH) {
        ms[t] = g_mpe[src + t];
        g_tf[bi*CH + t] = g_xi[src + t];
    }
    __syncthreads();
    int i = bi & 255;
    if (t < HID) {
        float d = 0.f;
        #pragma unroll
        for (int c = 0; c < CH; c++) d = fmaf(ms[c], w_p1[c*HID + t], d);
        g_B1T[(b*HID + t)*KSMP + i] = fmaf(d, g_s1[t], g_bias1[t]);
    }
    if (t == 0) g_nek[bi] = g_prob[b*NPTS + n];
}

// ---------------- pairwise kernel: 2 points/block + fused projection+scatter
__global__ void __launch_bounds__(256) pair_kernel(const float* w_p3, const float* b_p3,
                                                   const int* mask_idx, float* out) {
    __shared__ __align__(16) float  W2s[HID*HID];    // 4KB
    __shared__ __align__(16) float2 wiwe[2][KSMP];   // 4KB
    __shared__ __align__(16) float2 part[2][KSMP];   // 4KB
    __shared__ float A1s[2][HID], b2s[HID], w3s[HID];
    __shared__ float xa[2][CH], xb[2][CH];
    __shared__ float2 sumIE[2];
    __shared__ float bp3s;

    int blk = blockIdx.x;                            // 2048 blocks
    int b   = blk >> 10;
    int n0  = (blk & 1023) * 2;
    int bn  = b*NPTS + n0;
    int t   = threadIdx.x;                           // t = k

    for (int q = t; q < HID*HID; q += 256) W2s[q] = g_W2T[q];
    if (t < 2*HID) A1s[t >> 5][t & 31] = g_A1[bn*HID + t];
    if (t < HID) { b2s[t] = g_bias2[t]; w3s[t] = w_p3[t]; }
    if (t == 0) bp3s = b_p3[0];
    float ne = g_nek[b*KSMP + t];
    __syncthreads();

    // h1 for both points, packed in pairs; B1T column loaded once, used twice
    u64 h1a[HID/2], h1b[HID/2];
    #pragma unroll
    for (int i2 = 0; i2 < HID/2; i2++) {
        float blo = g_B1T[(b*HID + 2*i2    )*KSMP + t];
        float bhi = g_B1T[(b*HID + 2*i2 + 1)*KSMP + t];
        h1a[i2] = pack2(fmaxf(A1s[0][2*i2] + blo, 0.f), fmaxf(A1s[0][2*i2+1] + bhi, 0.f));
        h1b[i2] = pack2(fmaxf(A1s[1][2*i2] + blo, 0.f), fmaxf(A1s[1][2*i2+1] + bhi, 0.f));
    }

    // layer 2 (32x32, f32x2) + layer 3 (32->1)
    float accA = 0.f, accB = 0.f;
    #pragma unroll 4
    for (int j = 0; j < HID; j++) {
        const ulonglong2* wp = reinterpret_cast<const ulonglong2*>(&W2s[j*HID]);
        u64 za = pack2(b2s[j], 0.f);
        u64 zb = za;
        #pragma unroll
        for (int q = 0; q < 8; q++) {
            ulonglong2 w = wp[q];                    // broadcast LDS.128
            za = fma2(h1a[2*q],     w.x, za);
            za = fma2(h1a[2*q + 1], w.y, za);
            zb = fma2(h1b[2*q],     w.x, zb);
            zb = fma2(h1b[2*q + 1], w.y, zb);
        }
        float l, h;
        unpack2(za, l, h); accA = fmaf(fmaxf(l + h, 0.f), w3s[j], accA);
        unpack2(zb, l, h); accB = fmaf(fmaxf(l + h, 0.f), w3s[j], accB);
    }
    float Pa = 1.f / (1.f + expf(-(accA + bp3s)));
    float Pb = 1.f / (1.f + expf(-(accB + bp3s)));
    wiwe[0][t] = make_float2(Pa * ne, (1.f - Pa) * ne);
    wiwe[1][t] = make_float2(Pb * ne, (1.f - Pb) * ne);
    __syncthreads();

    // warps 0/1: scalar sums of wi/we per point
    if (t < 64) {
        int n = t >> 5, lane = t & 31;
        float si = 0.f, se = 0.f;
        #pragma unroll
        for (int kk = lane; kk < KSMP; kk += 32) {
            float2 v = wiwe[n][kk];
            si += v.x; se += v.y;
        }
        si = warpsum(si); se = warpsum(se);
        if (lane == 0) sumIE[n] = make_float2(si, se);
    }

    // weighted sums over tf: quarter q of k, channel c; tf LDG shared by points
    {
        int c = t & 63, q = t >> 6;
        u64 accA2 = 0ULL, accB2 = 0ULL;
        const float* tfb = g_tf + b*KSMP*CH;
        const u64* wv0 = reinterpret_cast<const u64*>(wiwe[0]);
        const u64* wv1 = reinterpret_cast<const u64*>(wiwe[1]);
        #pragma unroll 4
        for (int kk = q*64; kk < q*64 + 64; kk++) {
            float tfv = tfb[kk*CH + c];
            u64 t2 = pack2(tfv, tfv);
            accA2 = fma2(t2, wv0[kk], accA2);
            accB2 = fma2(t2, wv1[kk], accB2);
        }
        float pi, pe;
        unpack2(accA2, pi, pe); part[0][t] = make_float2(pi, pe);
        unpack2(accB2, pi, pe); part[1][t] = make_float2(pi, pe);
    }
    __syncthreads();

    if (t < 2*CH) {
        int n = t >> 6, c = t & 63;
        float2 p0 = part[n][c], p1 = part[n][64 + c], p2 = part[n][128 + c], p3 = part[n][192 + c];
        float si = p0.x + p1.x + p2.x + p3.x;
        float se = p0.y + p1.y + p2.y + p3.y;
        float2 s = sumIE[n];
        xa[n][c] = si / s.x;
        xb[n][c] = se / s.y;
    }
    __syncthreads();

    // fused ctx projection + scatter: t<128 -> (n, f); Weff reads are L2-hot
    if (t < 2*CH) {
        int n = t >> 6, f = t & 63;
        const float* Wf = g_Weff + CH*CH;            // rows [64:192)
        float acc = 0.f;
        #pragma unroll 8
        for (int j = 0; j < CH; j++) {
            acc = fmaf(xa[n][j], Wf[j*CH + f], acc);
            acc = fmaf(xb[n][j], Wf[(CH + j)*CH + f], acc);
        }
        int v = mask_idx[bn + n];
        out[(b*CH + f)*FLATN + v] += acc;
    }
}

// -----------------------------------------------------------------------------
extern "C" void kernel_launch(void* const* d_in, const int* in_sizes, int n_in,
                              void* d_out, int out_size) {
    const float* input    = (const float*)d_in[0];
    const int*   mask_idx = (const int*)  d_in[1];
    const float* w_ne1 = (const float*)d_in[2];
    const float* b_ne1 = (const float*)d_in[3];
    const float* g_ne  = (const float*)d_in[4];
    const float* be_ne = (const float*)d_in[5];
    const float* w_ne2 = (const float*)d_in[6];
    const float* b_ne2 = (const float*)d_in[7];
    const float* w_p1  = (const float*)d_in[8];
    const float* b_p1  = (const float*)d_in[9];
    const float* g_p1  = (const float*)d_in[10];
    const float* be_p1 = (const float*)d_in[11];
    const float* w_p2  = (const float*)d_in[12];
    const float* b_p2  = (const float*)d_in[13];
    const float* g_p2  = (const float*)d_in[14];
    const float* be_p2 = (const float*)d_in[15];
    const float* w_p3  = (const float*)d_in[16];
    const float* b_p3  = (const float*)d_in[17];
    const float* w_r1  = (const float*)d_in[18];
    const float* b_r1  = (const float*)d_in[19];
    const float* w_r2  = (const float*)d_in[20];
    const float* b_r2  = (const float*)d_in[21];
    float* out = (float*)d_out;

    weffprep_kernel<<<4*CH, CH>>>(w_r1, w_r2, b_ne1, g_ne, be_ne,
                                  b_p1, g_p1, be_p1, w_p2, b_p2, g_p2, be_p2,
                                  b_r1, b_r2);
    gxidense_kernel<<<GXIB + DENB + GUMB, 256>>>(input, mask_idx, w_ne1, w_ne2,
                                                 b_ne2, w_p1, out);
    samplegather_kernel<<<BSZ*KSMP, 256>>>(w_p1);
    pair_kernel<<<BSZ*NPTS/2, 256>>>(w_p3, b_p3, mask_idx, out);  // #4 -> ncu
}